// round 10
// baseline (speedup 1.0000x reference)
#include <cuda_runtime.h>
#include <cuda_bf16.h>
#include <math.h>
#include <stdint.h>

// ---------------------------------------------------------------------------
// Shapes
// ---------------------------------------------------------------------------
#define BB     32
#define TT     64
#define NN     128
#define F_IN   16
#define SOUT   16
#define DD     2048
#define NHEADS 16
#define DH     128
#define DFF    2048
#define LAYERS 2
#define NOUT   10
#define ROWS   (BB*TT)
#define DSZ    (ROWS*DD)        // 4M elements; one 2048x2048 matrix

// ---------------------------------------------------------------------------
// Static scratch (allocation-free rule)
// ---------------------------------------------------------------------------
__device__ float g_scratch[7ull * DSZ];                 // h,q,k,v,-,-,tmp
__device__ unsigned char g_mask[NN * NN];
__device__ __nv_bfloat16 g_wt_hi[12ull * DSZ];          // transposed weights hi
__device__ __nv_bfloat16 g_wt_lo[12ull * DSZ];          // transposed weights lo
__device__ __nv_bfloat16 g_a_hi[DSZ];                   // activation split A (hi)
__device__ __nv_bfloat16 g_a_lo[DSZ];                   // activation split A (lo)
__device__ __nv_bfloat16 g_b_hi[DSZ];                   // activation split B (hi)
__device__ __nv_bfloat16 g_b_lo[DSZ];                   // activation split B (lo)

// ---------------------------------------------------------------------------
// Helpers
// ---------------------------------------------------------------------------
__device__ __forceinline__ uint32_t smem_u32(const void* p) {
    uint32_t a;
    asm("{ .reg .u64 t; cvta.to.shared.u64 t, %1; cvt.u32.u64 %0, t; }" : "=r"(a) : "l"(p));
    return a;
}

#define CP_ASYNC16(saddr, gptr) \
    asm volatile("cp.async.cg.shared.global [%0], [%1], 16;" :: "r"(saddr), "l"(gptr) : "memory")
#define CP_COMMIT()  asm volatile("cp.async.commit_group;" ::: "memory")
#define CP_WAIT0()   asm volatile("cp.async.wait_group 0;" ::: "memory")
#define CP_WAIT1()   asm volatile("cp.async.wait_group 1;" ::: "memory")

__device__ __forceinline__ void ldsm_x4(uint32_t* r, uint32_t addr) {
    asm volatile("ldmatrix.sync.aligned.m8n8.x4.shared.b16 {%0,%1,%2,%3}, [%4];"
                 : "=r"(r[0]), "=r"(r[1]), "=r"(r[2]), "=r"(r[3]) : "r"(addr));
}
__device__ __forceinline__ void mma_bf16(float* d, const uint32_t* a, const uint32_t* b) {
    asm volatile(
        "mma.sync.aligned.m16n8k16.row.col.f32.bf16.bf16.f32 "
        "{%0,%1,%2,%3}, {%4,%5,%6,%7}, {%8,%9}, {%0,%1,%2,%3};"
        : "+f"(d[0]), "+f"(d[1]), "+f"(d[2]), "+f"(d[3])
        : "r"(a[0]), "r"(a[1]), "r"(a[2]), "r"(a[3]), "r"(b[0]), "r"(b[1]));
}

__device__ __forceinline__ void split_pair(float v, __nv_bfloat16& h, __nv_bfloat16& l) {
    h = __float2bfloat16(v);
    l = __float2bfloat16(v - __bfloat162float(h));
}

// ---------------------------------------------------------------------------
// Mask kernel
// ---------------------------------------------------------------------------
__global__ void mask_kernel(const float* __restrict__ V, const int* __restrict__ cls,
                            unsigned char* __restrict__ mask)
{
    int i = blockIdx.x, j = threadIdx.x;
    int c = *cls;
    float v = V[(size_t)c * NN * NN + i * NN + j];
    float a = (1.0f / (1.0f + expf(-v))) * (1.0f / (float)NN);
    mask[i * NN + j] = (a > 0.004f) || (i == j);
}

// ---------------------------------------------------------------------------
// GAT stage — register-tiled; emits h fp32 + hi/lo bf16 split
// ---------------------------------------------------------------------------
#define GAT_SMEM_FLOATS (2048+1024+1024+1024+64+64+64+64+16+8320+8320+16384)
#define GAT_SMEM_BYTES  (GAT_SMEM_FLOATS*4 + NN*NN)

__global__ __launch_bounds__(256) void gat_kernel(
    const float* __restrict__ X,
    const float* __restrict__ Wl, const float* __restrict__ bl,
    const float* __restrict__ Wr, const float* __restrict__ br,
    const float* __restrict__ att, const float* __restrict__ gbias,
    const float* __restrict__ Wfc, const float* __restrict__ bfc,
    const unsigned char* __restrict__ gmask,
    float* __restrict__ H,
    __nv_bfloat16* __restrict__ Hh, __nv_bfloat16* __restrict__ Hl)
{
    extern __shared__ float sm[];
    float* s_x   = sm;
    float* s_wl  = s_x   + 2048;
    float* s_wr  = s_wl  + 1024;
    float* s_wfc = s_wr  + 1024;
    float* s_att = s_wfc + 1024;
    float* s_bl  = s_att + 64;
    float* s_br  = s_bl  + 64;
    float* s_gb  = s_br  + 64;
    float* s_bfc = s_gb  + 64;
    float* s_xl  = s_bfc + 16;          // 128*65
    float* s_xr  = s_xl  + 8320;        // 128*65 ; reused as "out"
    float* s_e   = s_xr  + 8320;        // 128*128
    unsigned char* s_mask = (unsigned char*)(s_e + 16384);

    const int tid = threadIdx.x;
    const int r   = blockIdx.x;
    const float* xg = X + (size_t)r * (NN * F_IN);

    for (int i = tid; i < 2048; i += 256) s_x[i] = xg[i];
    for (int i = tid; i < 1024; i += 256) { s_wl[i] = Wl[i]; s_wr[i] = Wr[i]; s_wfc[i] = Wfc[i]; }
    if (tid < 64) { s_att[tid] = att[tid]; s_bl[tid] = bl[tid]; s_br[tid] = br[tid]; s_gb[tid] = gbias[tid]; }
    if (tid < 16) s_bfc[tid] = bfc[tid];
    for (int i = tid * 4; i < NN * NN; i += 256 * 4)
        *(uint32_t*)(s_mask + i) = *(const uint32_t*)(gmask + i);
    __syncthreads();

    for (int idx = tid; idx < 8192; idx += 256) {
        int i = idx >> 6, h = idx & 63;
        const float* xi = s_x + i * 16;
        float a = s_bl[h], b = s_br[h];
        #pragma unroll
        for (int f = 0; f < 16; f++) {
            float xv = xi[f];
            a += xv * s_wl[f * 64 + h];
            b += xv * s_wr[f * 64 + h];
        }
        s_xl[i * 65 + h] = a;
        s_xr[i * 65 + h] = b;
    }
    __syncthreads();

    // e[i][j] — 8x8 per-thread register tile
    {
        const int ib = tid >> 4;
        const int jb = tid & 15;
        float acc[8][8];
        #pragma unroll
        for (int a = 0; a < 8; a++)
            #pragma unroll
            for (int b = 0; b < 8; b++) acc[a][b] = 0.f;

        for (int h = 0; h < 64; h++) {
            float av = s_att[h];
            float xls[8], xrs[8];
            #pragma unroll
            for (int u = 0; u < 8; u++) xls[u] = s_xl[(ib + u * 16) * 65 + h];
            #pragma unroll
            for (int u = 0; u < 8; u++) xrs[u] = s_xr[(jb + u * 16) * 65 + h];
            #pragma unroll
            for (int ii = 0; ii < 8; ii++)
                #pragma unroll
                for (int jj = 0; jj < 8; jj++) {
                    float v = xls[ii] + xrs[jj];
                    v = (v > 0.f) ? v : 0.2f * v;
                    acc[ii][jj] = fmaf(av, v, acc[ii][jj]);
                }
        }
        #pragma unroll
        for (int ii = 0; ii < 8; ii++) {
            int i = ib + ii * 16;
            #pragma unroll
            for (int jj = 0; jj < 8; jj++) {
                int j = jb + jj * 16;
                s_e[i * 128 + j] = s_mask[i * 128 + j] ? acc[ii][jj] : -1e9f;
            }
        }
    }
    __syncthreads();

    if (tid < 128) {
        int j = tid;
        float m = -1e30f;
        for (int i = 0; i < 128; i++) m = fmaxf(m, s_e[i * 128 + j]);
        float s = 0.f;
        for (int i = 0; i < 128; i++) {
            float ev = __expf(s_e[i * 128 + j] - m);
            s_e[i * 128 + j] = ev;
            s += ev;
        }
        float inv = 1.0f / s;
        for (int i = 0; i < 128; i++) s_e[i * 128 + j] *= inv;
    }
    __syncthreads();

    // out[j][h] -> s_xr
    {
        const int hb = (tid & 15) * 4;
        const int jb = tid >> 4;
        float acc[8][4];
        #pragma unroll
        for (int a = 0; a < 8; a++)
            #pragma unroll
            for (int b = 0; b < 4; b++) acc[a][b] = 0.f;

        for (int i = 0; i < 128; i++) {
            float xv[4];
            #pragma unroll
            for (int u = 0; u < 4; u++) xv[u] = s_xl[i * 65 + hb + u];
            #pragma unroll
            for (int jj = 0; jj < 8; jj++) {
                float a = s_e[i * 128 + jb + jj * 16];
                #pragma unroll
                for (int u = 0; u < 4; u++)
                    acc[jj][u] = fmaf(a, xv[u], acc[jj][u]);
            }
        }
        __syncthreads();
        #pragma unroll
        for (int jj = 0; jj < 8; jj++) {
            int j = jb + jj * 16;
            #pragma unroll
            for (int u = 0; u < 4; u++)
                s_xr[j * 65 + hb + u] = acc[jj][u] + s_gb[hb + u];
        }
    }
    __syncthreads();

    // y = out @ Wfc + bfc -> H fp32 + hi/lo split
    {
        const int j  = tid >> 1;
        const int s0 = (tid & 1) * 8;
        float acc[8];
        #pragma unroll
        for (int u = 0; u < 8; u++) acc[u] = s_bfc[s0 + u];
        const float* oj = s_xr + j * 65;
        for (int h = 0; h < 64; h++) {
            float ov = oj[h];
            const float4 w0 = *(const float4*)&s_wfc[h * 16 + s0];
            const float4 w1 = *(const float4*)&s_wfc[h * 16 + s0 + 4];
            acc[0] = fmaf(ov, w0.x, acc[0]); acc[1] = fmaf(ov, w0.y, acc[1]);
            acc[2] = fmaf(ov, w0.z, acc[2]); acc[3] = fmaf(ov, w0.w, acc[3]);
            acc[4] = fmaf(ov, w1.x, acc[4]); acc[5] = fmaf(ov, w1.y, acc[5]);
            acc[6] = fmaf(ov, w1.z, acc[6]); acc[7] = fmaf(ov, w1.w, acc[7]);
        }
        size_t base = (size_t)r * DD + j * 16 + s0;
        #pragma unroll
        for (int u = 0; u < 8; u++) H[base + u] = acc[u];
        #pragma unroll
        for (int u = 0; u < 8; u++) {
            __nv_bfloat16 hh, ll;
            split_pair(acc[u], hh, ll);
            Hh[base + u] = hh;
            Hl[base + u] = ll;
        }
    }
}

// ---------------------------------------------------------------------------
// Weight transpose + bf16 split — all 12 matrices in one launch (z = slot)
// ---------------------------------------------------------------------------
struct TsplitArgs { const float* w[12]; };

__global__ __launch_bounds__(256) void tsplit_all_kernel(
    TsplitArgs args,
    __nv_bfloat16* __restrict__ ThBase, __nv_bfloat16* __restrict__ TlBase)
{
    __shared__ float t[32][33];
    const int slot = blockIdx.z;
    const float* W = args.w[slot];
    __nv_bfloat16* Th = ThBase + (size_t)slot * DSZ;
    __nv_bfloat16* Tl = TlBase + (size_t)slot * DSZ;

    const int bx = blockIdx.x, by = blockIdx.y;
    const int tx = threadIdx.x & 31, ty = threadIdx.x >> 5;
    #pragma unroll
    for (int i = 0; i < 4; i++) {
        int k = by * 32 + ty + i * 8;
        t[ty + i * 8][tx] = W[(size_t)k * 2048 + bx * 32 + tx];
    }
    __syncthreads();
    #pragma unroll
    for (int i = 0; i < 4; i++) {
        int n = bx * 32 + ty + i * 8;
        int k = by * 32 + tx;
        float v = t[tx][ty + i * 8];
        __nv_bfloat16 h, l;
        split_pair(v, h, l);
        Th[(size_t)n * 2048 + k] = h;
        Tl[(size_t)n * 2048 + k] = l;
    }
}

// ---------------------------------------------------------------------------
// bf16 split-GEMM via mma.sync (HMMA) — 3-stage cp.async pipeline
//   mode 0: C = acc+bias | 2: +resid | 3: relu -> split bf16 (Oh/Ol)
// ---------------------------------------------------------------------------
#define GEMM_BK        32
#define GEMM_LDS       40
#define GEMM_ARR_BYTES (128*GEMM_LDS*2)        // 10240
#define GEMM_STAGE     (4*GEMM_ARR_BYTES)      // 40960
#define GEMM_STAGES    3
#define GEMM_SMEM      (GEMM_STAGES*GEMM_STAGE)  // 122880

__device__ __forceinline__ void gemm_load_stage(
    const __nv_bfloat16* Ah, const __nv_bfloat16* Al,
    const __nv_bfloat16* Bh, const __nv_bfloat16* Bl,
    uint32_t sbase, int buf, int m0, int n0, int kc, int tid)
{
    uint32_t sb = sbase + buf * GEMM_STAGE;
    const __nv_bfloat16* gsrc[4];
    gsrc[0] = Ah + (size_t)m0 * 2048 + kc;
    gsrc[1] = Al + (size_t)m0 * 2048 + kc;
    gsrc[2] = Bh + (size_t)n0 * 2048 + kc;
    gsrc[3] = Bl + (size_t)n0 * 2048 + kc;
    #pragma unroll
    for (int arr = 0; arr < 4; arr++) {
        uint32_t abase = sb + arr * GEMM_ARR_BYTES;
        #pragma unroll
        for (int j = 0; j < 2; j++) {
            int idx = tid + j * 256;
            int row = idx >> 2;
            int cu  = idx & 3;
            uint32_t saddr = abase + row * (GEMM_LDS * 2) + cu * 16;
            const char* g = (const char*)gsrc[arr] + (size_t)row * 4096 + cu * 16;
            CP_ASYNC16(saddr, g);
        }
    }
}

__global__ __launch_bounds__(256, 1)
void gemm_mma_kernel(
    const __nv_bfloat16* __restrict__ Ah, const __nv_bfloat16* __restrict__ Al,
    const __nv_bfloat16* __restrict__ Bh, const __nv_bfloat16* __restrict__ Bl,
    const float* __restrict__ bias, const float* __restrict__ resid,
    float* __restrict__ C,
    __nv_bfloat16* __restrict__ Oh, __nv_bfloat16* __restrict__ Ol,
    int mode)
{
    extern __shared__ char dsm[];
    const uint32_t sbase = smem_u32(dsm);

    const int tid  = threadIdx.x;
    const int wid  = tid >> 5;
    const int lane = tid & 31;
    const int wm   = wid & 3;
    const int wn   = wid >> 2;
    const int m0   = blockIdx.y * 128;
    const int n0   = blockIdx.x * 128;

    const int aoff = (wm * 32 + (lane & 15)) * GEMM_LDS + (lane >> 4) * 8;
    const int boff = (wn * 64 + (lane >> 4) * 8 + (lane & 7)) * GEMM_LDS + ((lane >> 3) & 1) * 8;

    float acc[2][8][4];
    #pragma unroll
    for (int mt = 0; mt < 2; mt++)
        #pragma unroll
        for (int nt = 0; nt < 8; nt++)
            #pragma unroll
            for (int c = 0; c < 4; c++) acc[mt][nt][c] = 0.f;

    // prologue: stages 0,1 in flight
    gemm_load_stage(Ah, Al, Bh, Bl, sbase, 0, m0, n0, 0, tid);
    CP_COMMIT();
    gemm_load_stage(Ah, Al, Bh, Bl, sbase, 1, m0, n0, GEMM_BK, tid);
    CP_COMMIT();

    const int NCHUNK = 2048 / GEMM_BK;   // 64
    for (int i = 0; i < NCHUNK; i++) {
        CP_WAIT1();            // stage i loads complete (≤1 group outstanding)
        __syncthreads();       // all warps done with buf (i-1)%3; loads visible

        if (i + 2 < NCHUNK) {  // prefetch stage i+2 into buf (i+2)%3 == (i-1)%3
            gemm_load_stage(Ah, Al, Bh, Bl, sbase, (i + 2) % GEMM_STAGES,
                            m0, n0, (i + 2) * GEMM_BK, tid);
            CP_COMMIT();
        }

        const uint32_t sb   = sbase + (i % GEMM_STAGES) * GEMM_STAGE;
        const uint32_t aHiB = sb + 0 * GEMM_ARR_BYTES;
        const uint32_t aLoB = sb + 1 * GEMM_ARR_BYTES;
        const uint32_t bHiB = sb + 2 * GEMM_ARR_BYTES;
        const uint32_t bLoB = sb + 3 * GEMM_ARR_BYTES;

        #pragma unroll
        for (int kt = 0; kt < 2; kt++) {
            uint32_t aHi[2][4], aLo[2][4];
            #pragma unroll
            for (int mt = 0; mt < 2; mt++) {
                uint32_t ao = (aoff + mt * 16 * GEMM_LDS + kt * 16) * 2;
                ldsm_x4(aHi[mt], aHiB + ao);
                ldsm_x4(aLo[mt], aLoB + ao);
            }
            #pragma unroll
            for (int np = 0; np < 4; np++) {
                uint32_t bo = (boff + np * 16 * GEMM_LDS + kt * 16) * 2;
                uint32_t bHi[4], bLo[4];
                ldsm_x4(bHi, bHiB + bo);
                ldsm_x4(bLo, bLoB + bo);
                #pragma unroll
                for (int half = 0; half < 2; half++) {
                    int nt = np * 2 + half;
                    #pragma unroll
                    for (int mt = 0; mt < 2; mt++) {
                        mma_bf16(acc[mt][nt], aHi[mt], bHi + half * 2);
                        mma_bf16(acc[mt][nt], aHi[mt], bLo + half * 2);
                        mma_bf16(acc[mt][nt], aLo[mt], bHi + half * 2);
                    }
                }
            }
        }
        __syncthreads();       // compute done before buffer (i)%3 may be refilled at i+1? (refill target is (i+3)%3=i%3 at iter i+1) — guards reuse
    }

    // epilogue
    const int g  = lane >> 2;
    const int t2 = lane & 3;
    #pragma unroll
    for (int mt = 0; mt < 2; mt++) {
        #pragma unroll
        for (int nt = 0; nt < 8; nt++) {
            int row = m0 + wm * 32 + mt * 16 + g;
            int col = n0 + wn * 64 + nt * 8 + t2 * 2;
            float b0 = __ldg(bias + col), b1 = __ldg(bias + col + 1);
            #pragma unroll
            for (int half = 0; half < 2; half++) {
                int rr = row + half * 8;
                float v0 = acc[mt][nt][half * 2 + 0] + b0;
                float v1 = acc[mt][nt][half * 2 + 1] + b1;
                size_t off = (size_t)rr * 2048 + col;
                if (mode == 3) {
                    v0 = fmaxf(v0, 0.f); v1 = fmaxf(v1, 0.f);
                    __nv_bfloat16 h0, l0, h1, l1;
                    split_pair(v0, h0, l0);
                    split_pair(v1, h1, l1);
                    __nv_bfloat162 hp; hp.x = h0; hp.y = h1;
                    __nv_bfloat162 lp; lp.x = l0; lp.y = l1;
                    *(uint32_t*)(Oh + off) = *(uint32_t*)&hp;
                    *(uint32_t*)(Ol + off) = *(uint32_t*)&lp;
                } else {
                    if (mode == 2) {
                        const float2 rp = *(const float2*)(resid + off);
                        v0 += rp.x; v1 += rp.y;
                    }
                    float2 o; o.x = v0; o.y = v1;
                    *(float2*)(C + off) = o;
                }
            }
        }
    }
}

// ---------------------------------------------------------------------------
// Attention: writes hi/lo bf16 split of ao directly
// ---------------------------------------------------------------------------
#define ATTN_SMEM_BYTES ((8192 + 8256 + 8192 + 4160) * 4)

__global__ __launch_bounds__(256) void attn_kernel(
    const float* __restrict__ Q, const float* __restrict__ K,
    const float* __restrict__ V,
    __nv_bfloat16* __restrict__ AOh, __nv_bfloat16* __restrict__ AOl)
{
    extern __shared__ float sm[];
    float* sq = sm;
    float* sk = sq + 8192;
    float* sv = sk + 8256;
    float* sc = sv + 8192;

    const int tid = threadIdx.x;
    const int b   = blockIdx.x >> 4;
    const int hd  = blockIdx.x & 15;
    const size_t base = (size_t)(b * TT) * DD + hd * DH;
    const float SCALE = 0.08838834764831845f;

    for (int idx = tid; idx < 8192; idx += 256) {
        int t = idx >> 7, d = idx & 127;
        size_t g = base + (size_t)t * DD + d;
        sq[idx]          = Q[g] * SCALE;
        sk[t * 129 + d]  = K[g];
        sv[idx]          = V[g];
    }
    __syncthreads();

    for (int idx = tid; idx < 4096; idx += 256) {
        int t1 = idx >> 6, t2 = idx & 63;
        const float* qp = sq + t1 * 128;
        const float* kp = sk + t2 * 129;
        float acc = 0.f;
        #pragma unroll 16
        for (int d = 0; d < 128; d++) acc += qp[d] * kp[d];
        sc[t1 * 65 + t2] = acc;
    }
    __syncthreads();

    if (tid < 64) {
        float* rowp = sc + tid * 65;
        float m = -1e30f;
        for (int i = 0; i < 64; i++) m = fmaxf(m, rowp[i]);
        float s = 0.f;
        for (int i = 0; i < 64; i++) { float e = __expf(rowp[i] - m); rowp[i] = e; s += e; }
        float inv = 1.0f / s;
        for (int i = 0; i < 64; i++) rowp[i] *= inv;
    }
    __syncthreads();

    for (int idx = tid; idx < 8192; idx += 256) {
        int t = idx >> 7, d = idx & 127;
        const float* a = sc + t * 65;
        float acc = 0.f;
        #pragma unroll 16
        for (int t2 = 0; t2 < 64; t2++) acc += a[t2] * sv[t2 * 128 + d];
        __nv_bfloat16 hh, ll;
        split_pair(acc, hh, ll);
        size_t off = base + (size_t)t * DD + d;
        AOh[off] = hh;
        AOl[off] = ll;
    }
}

// ---------------------------------------------------------------------------
// LayerNorm: fp32 out + hi/lo bf16 split out
// ---------------------------------------------------------------------------
__global__ __launch_bounds__(256) void ln_kernel(
    const float* __restrict__ x, float* __restrict__ y,
    const float* __restrict__ g, const float* __restrict__ b,
    __nv_bfloat16* __restrict__ Yh, __nv_bfloat16* __restrict__ Yl)
{
    __shared__ float red[256];
    const int row = blockIdx.x, tid = threadIdx.x;
    const float* xr = x + (size_t)row * DD;

    float s = 0.f;
    for (int i = tid; i < DD; i += 256) s += xr[i];
    red[tid] = s; __syncthreads();
    for (int st = 128; st > 0; st >>= 1) { if (tid < st) red[tid] += red[tid + st]; __syncthreads(); }
    float mu = red[0] * (1.0f / DD);
    __syncthreads();

    float v = 0.f;
    for (int i = tid; i < DD; i += 256) { float d = xr[i] - mu; v += d * d; }
    red[tid] = v; __syncthreads();
    for (int st = 128; st > 0; st >>= 1) { if (tid < st) red[tid] += red[tid + st]; __syncthreads(); }
    float var = red[0] * (1.0f / DD);
    float inv = 1.0f / sqrtf(var + 1e-5f);

    float* yr = y + (size_t)row * DD;
    __nv_bfloat16* hr = Yh + (size_t)row * DD;
    __nv_bfloat16* lr = Yl + (size_t)row * DD;
    for (int i = tid; i < DD; i += 256) {
        float val = (xr[i] - mu) * inv * g[i] + b[i];
        yr[i] = val;
        __nv_bfloat16 hh, ll;
        split_pair(val, hh, ll);
        hr[i] = hh;
        lr[i] = ll;
    }
}

// ---------------------------------------------------------------------------
// Final projection
// ---------------------------------------------------------------------------
__global__ void out_kernel(const float* __restrict__ H, const float* __restrict__ Wout,
                           const float* __restrict__ bout, float* __restrict__ out)
{
    int b = blockIdx.x;
    int o = threadIdx.x >> 5;
    int lane = threadIdx.x & 31;
    if (o >= NOUT) return;
    const float* h = H + (size_t)(b * TT + TT - 1) * DD;
    float acc = 0.f;
    for (int i = lane; i < DD; i += 32)
        acc += h[i] * Wout[i * NOUT + o];
    #pragma unroll
    for (int s = 16; s > 0; s >>= 1)
        acc += __shfl_down_sync(0xffffffffu, acc, s);
    if (lane == 0) out[b * NOUT + o] = acc + bout[o];
}

// ---------------------------------------------------------------------------
// Launch
// ---------------------------------------------------------------------------
extern "C" void kernel_launch(void* const* d_in, const int* in_sizes, int n_in,
                              void* d_out, int out_size)
{
    (void)in_sizes; (void)n_in; (void)out_size;

    const float* X      = (const float*)d_in[0];
    const float* V_Adap = (const float*)d_in[1];
    const float* Wl     = (const float*)d_in[2];
    const float* bl     = (const float*)d_in[3];
    const float* Wr     = (const float*)d_in[4];
    const float* br     = (const float*)d_in[5];
    const float* att    = (const float*)d_in[6];
    const float* gbias  = (const float*)d_in[7];
    const float* Wfc    = (const float*)d_in[8];
    const float* bfc    = (const float*)d_in[9];
    const float* Wq     = (const float*)d_in[10];
    const float* bq     = (const float*)d_in[11];
    const float* Wk     = (const float*)d_in[12];
    const float* bk     = (const float*)d_in[13];
    const float* Wv     = (const float*)d_in[14];
    const float* bv     = (const float*)d_in[15];
    const float* Wo     = (const float*)d_in[16];
    const float* bo     = (const float*)d_in[17];
    const float* ln1g   = (const float*)d_in[18];
    const float* ln1b   = (const float*)d_in[19];
    const float* W1     = (const float*)d_in[20];
    const float* b1     = (const float*)d_in[21];
    const float* W2     = (const float*)d_in[22];
    const float* b2     = (const float*)d_in[23];
    const float* ln2g   = (const float*)d_in[24];
    const float* ln2b   = (const float*)d_in[25];
    const float* Wout   = (const float*)d_in[26];
    const float* bout   = (const float*)d_in[27];
    const int*   cls    = (const int*)d_in[28];

    float* base = nullptr;
    unsigned char* maskp = nullptr;
    __nv_bfloat16 *wth = nullptr, *wtl = nullptr, *ah = nullptr, *al = nullptr;
    __nv_bfloat16 *bh = nullptr, *blo = nullptr;
    cudaGetSymbolAddress((void**)&base,  g_scratch);
    cudaGetSymbolAddress((void**)&maskp, g_mask);
    cudaGetSymbolAddress((void**)&wth,   g_wt_hi);
    cudaGetSymbolAddress((void**)&wtl,   g_wt_lo);
    cudaGetSymbolAddress((void**)&ah,    g_a_hi);
    cudaGetSymbolAddress((void**)&al,    g_a_lo);
    cudaGetSymbolAddress((void**)&bh,    g_b_hi);
    cudaGetSymbolAddress((void**)&blo,   g_b_lo);

    float* h  = base + 0ull * DSZ;
    float* q  = base + 1ull * DSZ;
    float* k  = base + 2ull * DSZ;
    float* v  = base + 3ull * DSZ;
    float* t  = base + 6ull * DSZ;

    cudaFuncSetAttribute(gat_kernel,      cudaFuncAttributeMaxDynamicSharedMemorySize, GAT_SMEM_BYTES);
    cudaFuncSetAttribute(attn_kernel,     cudaFuncAttributeMaxDynamicSharedMemorySize, ATTN_SMEM_BYTES);
    cudaFuncSetAttribute(gemm_mma_kernel, cudaFuncAttributeMaxDynamicSharedMemorySize, GEMM_SMEM);

    mask_kernel<<<NN, NN>>>(V_Adap, cls, maskp);
    gat_kernel<<<ROWS, 256, GAT_SMEM_BYTES>>>(X, Wl, bl, Wr, br, att, gbias, Wfc, bfc, maskp,
                                              h, ah, al);

    // pre-transpose + split all 12 weight matrices in ONE launch
    {
        TsplitArgs ta;
        for (int l = 0; l < LAYERS; l++) {
            ta.w[l * 6 + 0] = Wq + (size_t)l * DSZ;
            ta.w[l * 6 + 1] = Wk + (size_t)l * DSZ;
            ta.w[l * 6 + 2] = Wv + (size_t)l * DSZ;
            ta.w[l * 6 + 3] = Wo + (size_t)l * DSZ;
            ta.w[l * 6 + 4] = W1 + (size_t)l * DSZ;
            ta.w[l * 6 + 5] = W2 + (size_t)l * DSZ;
        }
        dim3 tg(64, 64, 12);
        tsplit_all_kernel<<<tg, 256>>>(ta, wth, wtl);
    }

    dim3 gg(16, 16);
    for (int l = 0; l < LAYERS; l++) {
        size_t s0 = (size_t)(l * 6 + 0) * DSZ;
        size_t s1 = (size_t)(l * 6 + 1) * DSZ;
        size_t s2 = (size_t)(l * 6 + 2) * DSZ;
        size_t s3 = (size_t)(l * 6 + 3) * DSZ;
        size_t s4 = (size_t)(l * 6 + 4) * DSZ;
        size_t s5 = (size_t)(l * 6 + 5) * DSZ;

        gemm_mma_kernel<<<gg, 256, GEMM_SMEM>>>(ah, al, wth + s0, wtl + s0, bq + l * DD,
                                                nullptr, q, nullptr, nullptr, 0);
        gemm_mma_kernel<<<gg, 256, GEMM_SMEM>>>(ah, al, wth + s1, wtl + s1, bk + l * DD,
                                                nullptr, k, nullptr, nullptr, 0);
        gemm_mma_kernel<<<gg, 256, GEMM_SMEM>>>(ah, al, wth + s2, wtl + s2, bv + l * DD,
                                                nullptr, v, nullptr, nullptr, 0);
        attn_kernel<<<BB * NHEADS, 256, ATTN_SMEM_BYTES>>>(q, k, v, ah, al);
        gemm_mma_kernel<<<gg, 256, GEMM_SMEM>>>(ah, al, wth + s3, wtl + s3, bo + l * DD,
                                                h, t, nullptr, nullptr, 2);
        ln_kernel<<<ROWS, 256>>>(t, h, ln1g + l * DD, ln1b + l * DD, ah, al);
        gemm_mma_kernel<<<gg, 256, GEMM_SMEM>>>(ah, al, wth + s4, wtl + s4, b1 + l * DFF,
                                                nullptr, nullptr, bh, blo, 3);
        gemm_mma_kernel<<<gg, 256, GEMM_SMEM>>>(bh, blo, wth + s5, wtl + s5, b2 + l * DD,
                                                h, t, nullptr, nullptr, 2);
        ln_kernel<<<ROWS, 256>>>(t, h, ln2g + l * DD, ln2b + l * DD, ah, al);
    }

    out_kernel<<<BB, 320>>>(h, Wout, bout, (float*)d_out);
}

// round 11
// speedup vs baseline: 1.0569x; 1.0569x over previous
#include <cuda_runtime.h>
#include <cuda_bf16.h>
#include <math.h>
#include <stdint.h>

// ---------------------------------------------------------------------------
// Shapes
// ---------------------------------------------------------------------------
#define BB     32
#define TT     64
#define NN     128
#define F_IN   16
#define SOUT   16
#define DD     2048
#define NHEADS 16
#define DH     128
#define DFF    2048
#define LAYERS 2
#define NOUT   10
#define ROWS   (BB*TT)
#define DSZ    (ROWS*DD)        // 4M elements; one 2048x2048 matrix

// ---------------------------------------------------------------------------
// Static scratch (allocation-free rule)
// ---------------------------------------------------------------------------
__device__ float g_scratch[7ull * DSZ];                 // h,q,k,v,-,-,tmp
__device__ unsigned char g_mask[NN * NN];
__device__ __nv_bfloat16 g_wt_hi[12ull * DSZ];          // transposed weights hi
__device__ __nv_bfloat16 g_wt_lo[12ull * DSZ];          // transposed weights lo
__device__ __nv_bfloat16 g_a_hi[DSZ];                   // activation split A (hi)
__device__ __nv_bfloat16 g_a_lo[DSZ];                   // activation split A (lo)
__device__ __nv_bfloat16 g_b_hi[DSZ];                   // activation split B (hi)
__device__ __nv_bfloat16 g_b_lo[DSZ];                   // activation split B (lo)

// ---------------------------------------------------------------------------
// Helpers
// ---------------------------------------------------------------------------
__device__ __forceinline__ uint32_t smem_u32(const void* p) {
    uint32_t a;
    asm("{ .reg .u64 t; cvta.to.shared.u64 t, %1; cvt.u32.u64 %0, t; }" : "=r"(a) : "l"(p));
    return a;
}

#define CP_ASYNC16(saddr, gptr) \
    asm volatile("cp.async.cg.shared.global [%0], [%1], 16;" :: "r"(saddr), "l"(gptr) : "memory")
#define CP_COMMIT()  asm volatile("cp.async.commit_group;" ::: "memory")
#define CP_WAIT0()   asm volatile("cp.async.wait_group 0;" ::: "memory")

__device__ __forceinline__ void ldsm_x4(uint32_t* r, uint32_t addr) {
    asm volatile("ldmatrix.sync.aligned.m8n8.x4.shared.b16 {%0,%1,%2,%3}, [%4];"
                 : "=r"(r[0]), "=r"(r[1]), "=r"(r[2]), "=r"(r[3]) : "r"(addr));
}
__device__ __forceinline__ void mma_bf16(float* d, const uint32_t* a, const uint32_t* b) {
    asm volatile(
        "mma.sync.aligned.m16n8k16.row.col.f32.bf16.bf16.f32 "
        "{%0,%1,%2,%3}, {%4,%5,%6,%7}, {%8,%9}, {%0,%1,%2,%3};"
        : "+f"(d[0]), "+f"(d[1]), "+f"(d[2]), "+f"(d[3])
        : "r"(a[0]), "r"(a[1]), "r"(a[2]), "r"(a[3]), "r"(b[0]), "r"(b[1]));
}

__device__ __forceinline__ void split_pair(float v, __nv_bfloat16& h, __nv_bfloat16& l) {
    h = __float2bfloat16(v);
    l = __float2bfloat16(v - __bfloat162float(h));
}

// ---------------------------------------------------------------------------
// Mask kernel
// ---------------------------------------------------------------------------
__global__ void mask_kernel(const float* __restrict__ V, const int* __restrict__ cls,
                            unsigned char* __restrict__ mask)
{
    int i = blockIdx.x, j = threadIdx.x;
    int c = *cls;
    float v = V[(size_t)c * NN * NN + i * NN + j];
    float a = (1.0f / (1.0f + expf(-v))) * (1.0f / (float)NN);
    mask[i * NN + j] = (a > 0.004f) || (i == j);
}

// ---------------------------------------------------------------------------
// GAT stage — register-tiled; emits h fp32 + hi/lo bf16 split
// ---------------------------------------------------------------------------
#define GAT_SMEM_FLOATS (2048+1024+1024+1024+64+64+64+64+16+8320+8320+16384)
#define GAT_SMEM_BYTES  (GAT_SMEM_FLOATS*4 + NN*NN)

__global__ __launch_bounds__(256) void gat_kernel(
    const float* __restrict__ X,
    const float* __restrict__ Wl, const float* __restrict__ bl,
    const float* __restrict__ Wr, const float* __restrict__ br,
    const float* __restrict__ att, const float* __restrict__ gbias,
    const float* __restrict__ Wfc, const float* __restrict__ bfc,
    const unsigned char* __restrict__ gmask,
    float* __restrict__ H,
    __nv_bfloat16* __restrict__ Hh, __nv_bfloat16* __restrict__ Hl)
{
    extern __shared__ float sm[];
    float* s_x   = sm;
    float* s_wl  = s_x   + 2048;
    float* s_wr  = s_wl  + 1024;
    float* s_wfc = s_wr  + 1024;
    float* s_att = s_wfc + 1024;
    float* s_bl  = s_att + 64;
    float* s_br  = s_bl  + 64;
    float* s_gb  = s_br  + 64;
    float* s_bfc = s_gb  + 64;
    float* s_xl  = s_bfc + 16;          // 128*65
    float* s_xr  = s_xl  + 8320;        // 128*65 ; reused as "out"
    float* s_e   = s_xr  + 8320;        // 128*128
    unsigned char* s_mask = (unsigned char*)(s_e + 16384);

    const int tid = threadIdx.x;
    const int r   = blockIdx.x;
    const float* xg = X + (size_t)r * (NN * F_IN);

    for (int i = tid; i < 2048; i += 256) s_x[i] = xg[i];
    for (int i = tid; i < 1024; i += 256) { s_wl[i] = Wl[i]; s_wr[i] = Wr[i]; s_wfc[i] = Wfc[i]; }
    if (tid < 64) { s_att[tid] = att[tid]; s_bl[tid] = bl[tid]; s_br[tid] = br[tid]; s_gb[tid] = gbias[tid]; }
    if (tid < 16) s_bfc[tid] = bfc[tid];
    for (int i = tid * 4; i < NN * NN; i += 256 * 4)
        *(uint32_t*)(s_mask + i) = *(const uint32_t*)(gmask + i);
    __syncthreads();

    for (int idx = tid; idx < 8192; idx += 256) {
        int i = idx >> 6, h = idx & 63;
        const float* xi = s_x + i * 16;
        float a = s_bl[h], b = s_br[h];
        #pragma unroll
        for (int f = 0; f < 16; f++) {
            float xv = xi[f];
            a += xv * s_wl[f * 64 + h];
            b += xv * s_wr[f * 64 + h];
        }
        s_xl[i * 65 + h] = a;
        s_xr[i * 65 + h] = b;
    }
    __syncthreads();

    // e[i][j] — 8x8 per-thread register tile
    {
        const int ib = tid >> 4;
        const int jb = tid & 15;
        float acc[8][8];
        #pragma unroll
        for (int a = 0; a < 8; a++)
            #pragma unroll
            for (int b = 0; b < 8; b++) acc[a][b] = 0.f;

        for (int h = 0; h < 64; h++) {
            float av = s_att[h];
            float xls[8], xrs[8];
            #pragma unroll
            for (int u = 0; u < 8; u++) xls[u] = s_xl[(ib + u * 16) * 65 + h];
            #pragma unroll
            for (int u = 0; u < 8; u++) xrs[u] = s_xr[(jb + u * 16) * 65 + h];
            #pragma unroll
            for (int ii = 0; ii < 8; ii++)
                #pragma unroll
                for (int jj = 0; jj < 8; jj++) {
                    float v = xls[ii] + xrs[jj];
                    v = (v > 0.f) ? v : 0.2f * v;
                    acc[ii][jj] = fmaf(av, v, acc[ii][jj]);
                }
        }
        #pragma unroll
        for (int ii = 0; ii < 8; ii++) {
            int i = ib + ii * 16;
            #pragma unroll
            for (int jj = 0; jj < 8; jj++) {
                int j = jb + jj * 16;
                s_e[i * 128 + j] = s_mask[i * 128 + j] ? acc[ii][jj] : -1e9f;
            }
        }
    }
    __syncthreads();

    if (tid < 128) {
        int j = tid;
        float m = -1e30f;
        for (int i = 0; i < 128; i++) m = fmaxf(m, s_e[i * 128 + j]);
        float s = 0.f;
        for (int i = 0; i < 128; i++) {
            float ev = __expf(s_e[i * 128 + j] - m);
            s_e[i * 128 + j] = ev;
            s += ev;
        }
        float inv = 1.0f / s;
        for (int i = 0; i < 128; i++) s_e[i * 128 + j] *= inv;
    }
    __syncthreads();

    // out[j][h] -> s_xr
    {
        const int hb = (tid & 15) * 4;
        const int jb = tid >> 4;
        float acc[8][4];
        #pragma unroll
        for (int a = 0; a < 8; a++)
            #pragma unroll
            for (int b = 0; b < 4; b++) acc[a][b] = 0.f;

        for (int i = 0; i < 128; i++) {
            float xv[4];
            #pragma unroll
            for (int u = 0; u < 4; u++) xv[u] = s_xl[i * 65 + hb + u];
            #pragma unroll
            for (int jj = 0; jj < 8; jj++) {
                float a = s_e[i * 128 + jb + jj * 16];
                #pragma unroll
                for (int u = 0; u < 4; u++)
                    acc[jj][u] = fmaf(a, xv[u], acc[jj][u]);
            }
        }
        __syncthreads();
        #pragma unroll
        for (int jj = 0; jj < 8; jj++) {
            int j = jb + jj * 16;
            #pragma unroll
            for (int u = 0; u < 4; u++)
                s_xr[j * 65 + hb + u] = acc[jj][u] + s_gb[hb + u];
        }
    }
    __syncthreads();

    // y = out @ Wfc + bfc -> H fp32 + hi/lo split
    {
        const int j  = tid >> 1;
        const int s0 = (tid & 1) * 8;
        float acc[8];
        #pragma unroll
        for (int u = 0; u < 8; u++) acc[u] = s_bfc[s0 + u];
        const float* oj = s_xr + j * 65;
        for (int h = 0; h < 64; h++) {
            float ov = oj[h];
            const float4 w0 = *(const float4*)&s_wfc[h * 16 + s0];
            const float4 w1 = *(const float4*)&s_wfc[h * 16 + s0 + 4];
            acc[0] = fmaf(ov, w0.x, acc[0]); acc[1] = fmaf(ov, w0.y, acc[1]);
            acc[2] = fmaf(ov, w0.z, acc[2]); acc[3] = fmaf(ov, w0.w, acc[3]);
            acc[4] = fmaf(ov, w1.x, acc[4]); acc[5] = fmaf(ov, w1.y, acc[5]);
            acc[6] = fmaf(ov, w1.z, acc[6]); acc[7] = fmaf(ov, w1.w, acc[7]);
        }
        size_t base = (size_t)r * DD + j * 16 + s0;
        #pragma unroll
        for (int u = 0; u < 8; u++) H[base + u] = acc[u];
        #pragma unroll
        for (int u = 0; u < 8; u++) {
            __nv_bfloat16 hh, ll;
            split_pair(acc[u], hh, ll);
            Hh[base + u] = hh;
            Hl[base + u] = ll;
        }
    }
}

// ---------------------------------------------------------------------------
// Weight transpose + bf16 split — all 12 matrices in one launch (z = slot)
// ---------------------------------------------------------------------------
struct TsplitArgs { const float* w[12]; };

__global__ __launch_bounds__(256) void tsplit_all_kernel(
    TsplitArgs args,
    __nv_bfloat16* __restrict__ ThBase, __nv_bfloat16* __restrict__ TlBase)
{
    __shared__ float t[32][33];
    const int slot = blockIdx.z;
    const float* W = args.w[slot];
    __nv_bfloat16* Th = ThBase + (size_t)slot * DSZ;
    __nv_bfloat16* Tl = TlBase + (size_t)slot * DSZ;

    const int bx = blockIdx.x, by = blockIdx.y;
    const int tx = threadIdx.x & 31, ty = threadIdx.x >> 5;
    #pragma unroll
    for (int i = 0; i < 4; i++) {
        int k = by * 32 + ty + i * 8;
        t[ty + i * 8][tx] = W[(size_t)k * 2048 + bx * 32 + tx];
    }
    __syncthreads();
    #pragma unroll
    for (int i = 0; i < 4; i++) {
        int n = bx * 32 + ty + i * 8;
        int k = by * 32 + tx;
        float v = t[tx][ty + i * 8];
        __nv_bfloat16 h, l;
        split_pair(v, h, l);
        Th[(size_t)n * 2048 + k] = h;
        Tl[(size_t)n * 2048 + k] = l;
    }
}

// ---------------------------------------------------------------------------
// bf16 split-GEMM via mma.sync (HMMA) — 512 threads, 16 warps (4/SMSP),
// warp tile 32x32, 2-stage cp.async pipeline (R9 structure).
//   mode 0: C = acc+bias | 2: +resid | 3: relu -> split bf16 (Oh/Ol)
// ---------------------------------------------------------------------------
#define GEMM_THREADS   512
#define GEMM_BK        32
#define GEMM_LDS       40
#define GEMM_ARR_BYTES (128*GEMM_LDS*2)        // 10240
#define GEMM_STAGE     (4*GEMM_ARR_BYTES)      // 40960
#define GEMM_SMEM      (2*GEMM_STAGE)          // 81920

__device__ __forceinline__ void gemm_load_stage(
    const __nv_bfloat16* Ah, const __nv_bfloat16* Al,
    const __nv_bfloat16* Bh, const __nv_bfloat16* Bl,
    uint32_t sbase, int buf, int m0, int n0, int kc, int tid)
{
    uint32_t sb = sbase + buf * GEMM_STAGE;
    const __nv_bfloat16* gsrc[4];
    gsrc[0] = Ah + (size_t)m0 * 2048 + kc;
    gsrc[1] = Al + (size_t)m0 * 2048 + kc;
    gsrc[2] = Bh + (size_t)n0 * 2048 + kc;
    gsrc[3] = Bl + (size_t)n0 * 2048 + kc;
    const int row = tid >> 2;          // 0..127
    const int cu  = tid & 3;           // 16B chunk in 64B row
    const uint32_t soff = row * (GEMM_LDS * 2) + cu * 16;
    const size_t  goff = (size_t)row * 4096 + cu * 16;
    #pragma unroll
    for (int arr = 0; arr < 4; arr++) {
        CP_ASYNC16(sb + arr * GEMM_ARR_BYTES + soff, (const char*)gsrc[arr] + goff);
    }
}

__global__ __launch_bounds__(GEMM_THREADS, 1)
void gemm_mma_kernel(
    const __nv_bfloat16* __restrict__ Ah, const __nv_bfloat16* __restrict__ Al,
    const __nv_bfloat16* __restrict__ Bh, const __nv_bfloat16* __restrict__ Bl,
    const float* __restrict__ bias, const float* __restrict__ resid,
    float* __restrict__ C,
    __nv_bfloat16* __restrict__ Oh, __nv_bfloat16* __restrict__ Ol,
    int mode)
{
    extern __shared__ char dsm[];
    const uint32_t sbase = smem_u32(dsm);

    const int tid  = threadIdx.x;
    const int wid  = tid >> 5;
    const int lane = tid & 31;
    const int wm   = wid & 3;          // m offset 32*wm
    const int wn   = wid >> 2;         // 0..3, n offset 32*wn
    const int m0   = blockIdx.y * 128;
    const int n0   = blockIdx.x * 128;

    const int aoff = (wm * 32 + (lane & 15)) * GEMM_LDS + (lane >> 4) * 8;
    const int boff = (wn * 32 + (lane >> 4) * 8 + (lane & 7)) * GEMM_LDS + ((lane >> 3) & 1) * 8;

    float acc[2][4][4];
    #pragma unroll
    for (int mt = 0; mt < 2; mt++)
        #pragma unroll
        for (int nt = 0; nt < 4; nt++)
            #pragma unroll
            for (int c = 0; c < 4; c++) acc[mt][nt][c] = 0.f;

    gemm_load_stage(Ah, Al, Bh, Bl, sbase, 0, m0, n0, 0, tid);
    CP_COMMIT();
    CP_WAIT0();
    __syncthreads();

    const int NCHUNK = 2048 / GEMM_BK;   // 64
    for (int i = 0; i < NCHUNK; i++) {
        const int buf = i & 1;
        if (i + 1 < NCHUNK) {
            gemm_load_stage(Ah, Al, Bh, Bl, sbase, buf ^ 1, m0, n0, (i + 1) * GEMM_BK, tid);
            CP_COMMIT();
        }

        const uint32_t sb   = sbase + buf * GEMM_STAGE;
        const uint32_t aHiB = sb + 0 * GEMM_ARR_BYTES;
        const uint32_t aLoB = sb + 1 * GEMM_ARR_BYTES;
        const uint32_t bHiB = sb + 2 * GEMM_ARR_BYTES;
        const uint32_t bLoB = sb + 3 * GEMM_ARR_BYTES;

        #pragma unroll
        for (int kt = 0; kt < 2; kt++) {
            uint32_t aHi[2][4], aLo[2][4];
            #pragma unroll
            for (int mt = 0; mt < 2; mt++) {
                uint32_t ao = (aoff + mt * 16 * GEMM_LDS + kt * 16) * 2;
                ldsm_x4(aHi[mt], aHiB + ao);
                ldsm_x4(aLo[mt], aLoB + ao);
            }
            #pragma unroll
            for (int np = 0; np < 2; np++) {
                uint32_t bo = (boff + np * 16 * GEMM_LDS + kt * 16) * 2;
                uint32_t bHi[4], bLo[4];
                ldsm_x4(bHi, bHiB + bo);
                ldsm_x4(bLo, bLoB + bo);
                #pragma unroll
                for (int half = 0; half < 2; half++) {
                    int nt = np * 2 + half;
                    #pragma unroll
                    for (int mt = 0; mt < 2; mt++) {
                        mma_bf16(acc[mt][nt], aHi[mt], bHi + half * 2);
                        mma_bf16(acc[mt][nt], aHi[mt], bLo + half * 2);
                        mma_bf16(acc[mt][nt], aLo[mt], bHi + half * 2);
                    }
                }
            }
        }

        CP_WAIT0();
        __syncthreads();
    }

    // epilogue
    const int g  = lane >> 2;
    const int t2 = lane & 3;
    #pragma unroll
    for (int mt = 0; mt < 2; mt++) {
        #pragma unroll
        for (int nt = 0; nt < 4; nt++) {
            int row = m0 + wm * 32 + mt * 16 + g;
            int col = n0 + wn * 32 + nt * 8 + t2 * 2;
            float b0 = __ldg(bias + col), b1 = __ldg(bias + col + 1);
            #pragma unroll
            for (int half = 0; half < 2; half++) {
                int rr = row + half * 8;
                float v0 = acc[mt][nt][half * 2 + 0] + b0;
                float v1 = acc[mt][nt][half * 2 + 1] + b1;
                size_t off = (size_t)rr * 2048 + col;
                if (mode == 3) {
                    v0 = fmaxf(v0, 0.f); v1 = fmaxf(v1, 0.f);
                    __nv_bfloat16 h0, l0, h1, l1;
                    split_pair(v0, h0, l0);
                    split_pair(v1, h1, l1);
                    __nv_bfloat162 hp; hp.x = h0; hp.y = h1;
                    __nv_bfloat162 lp; lp.x = l0; lp.y = l1;
                    *(uint32_t*)(Oh + off) = *(uint32_t*)&hp;
                    *(uint32_t*)(Ol + off) = *(uint32_t*)&lp;
                } else {
                    if (mode == 2) {
                        const float2 rp = *(const float2*)(resid + off);
                        v0 += rp.x; v1 += rp.y;
                    }
                    float2 o; o.x = v0; o.y = v1;
                    *(float2*)(C + off) = o;
                }
            }
        }
    }
}

// ---------------------------------------------------------------------------
// Attention: writes hi/lo bf16 split of ao directly
// ---------------------------------------------------------------------------
#define ATTN_SMEM_BYTES ((8192 + 8256 + 8192 + 4160) * 4)

__global__ __launch_bounds__(256) void attn_kernel(
    const float* __restrict__ Q, const float* __restrict__ K,
    const float* __restrict__ V,
    __nv_bfloat16* __restrict__ AOh, __nv_bfloat16* __restrict__ AOl)
{
    extern __shared__ float sm[];
    float* sq = sm;
    float* sk = sq + 8192;
    float* sv = sk + 8256;
    float* sc = sv + 8192;

    const int tid = threadIdx.x;
    const int b   = blockIdx.x >> 4;
    const int hd  = blockIdx.x & 15;
    const size_t base = (size_t)(b * TT) * DD + hd * DH;
    const float SCALE = 0.08838834764831845f;

    for (int idx = tid; idx < 8192; idx += 256) {
        int t = idx >> 7, d = idx & 127;
        size_t g = base + (size_t)t * DD + d;
        sq[idx]          = Q[g] * SCALE;
        sk[t * 129 + d]  = K[g];
        sv[idx]          = V[g];
    }
    __syncthreads();

    for (int idx = tid; idx < 4096; idx += 256) {
        int t1 = idx >> 6, t2 = idx & 63;
        const float* qp = sq + t1 * 128;
        const float* kp = sk + t2 * 129;
        float acc = 0.f;
        #pragma unroll 16
        for (int d = 0; d < 128; d++) acc += qp[d] * kp[d];
        sc[t1 * 65 + t2] = acc;
    }
    __syncthreads();

    if (tid < 64) {
        float* rowp = sc + tid * 65;
        float m = -1e30f;
        for (int i = 0; i < 64; i++) m = fmaxf(m, rowp[i]);
        float s = 0.f;
        for (int i = 0; i < 64; i++) { float e = __expf(rowp[i] - m); rowp[i] = e; s += e; }
        float inv = 1.0f / s;
        for (int i = 0; i < 64; i++) rowp[i] *= inv;
    }
    __syncthreads();

    for (int idx = tid; idx < 8192; idx += 256) {
        int t = idx >> 7, d = idx & 127;
        const float* a = sc + t * 65;
        float acc = 0.f;
        #pragma unroll 16
        for (int t2 = 0; t2 < 64; t2++) acc += a[t2] * sv[t2 * 128 + d];
        __nv_bfloat16 hh, ll;
        split_pair(acc, hh, ll);
        size_t off = base + (size_t)t * DD + d;
        AOh[off] = hh;
        AOl[off] = ll;
    }
}

// ---------------------------------------------------------------------------
// LayerNorm: fp32 out + hi/lo bf16 split out
// ---------------------------------------------------------------------------
__global__ __launch_bounds__(256) void ln_kernel(
    const float* __restrict__ x, float* __restrict__ y,
    const float* __restrict__ g, const float* __restrict__ b,
    __nv_bfloat16* __restrict__ Yh, __nv_bfloat16* __restrict__ Yl)
{
    __shared__ float red[256];
    const int row = blockIdx.x, tid = threadIdx.x;
    const float* xr = x + (size_t)row * DD;

    float s = 0.f;
    for (int i = tid; i < DD; i += 256) s += xr[i];
    red[tid] = s; __syncthreads();
    for (int st = 128; st > 0; st >>= 1) { if (tid < st) red[tid] += red[tid + st]; __syncthreads(); }
    float mu = red[0] * (1.0f / DD);
    __syncthreads();

    float v = 0.f;
    for (int i = tid; i < DD; i += 256) { float d = xr[i] - mu; v += d * d; }
    red[tid] = v; __syncthreads();
    for (int st = 128; st > 0; st >>= 1) { if (tid < st) red[tid] += red[tid + st]; __syncthreads(); }
    float var = red[0] * (1.0f / DD);
    float inv = 1.0f / sqrtf(var + 1e-5f);

    float* yr = y + (size_t)row * DD;
    __nv_bfloat16* hr = Yh + (size_t)row * DD;
    __nv_bfloat16* lr = Yl + (size_t)row * DD;
    for (int i = tid; i < DD; i += 256) {
        float val = (xr[i] - mu) * inv * g[i] + b[i];
        yr[i] = val;
        __nv_bfloat16 hh, ll;
        split_pair(val, hh, ll);
        hr[i] = hh;
        lr[i] = ll;
    }
}

// ---------------------------------------------------------------------------
// Final projection
// ---------------------------------------------------------------------------
__global__ void out_kernel(const float* __restrict__ H, const float* __restrict__ Wout,
                           const float* __restrict__ bout, float* __restrict__ out)
{
    int b = blockIdx.x;
    int o = threadIdx.x >> 5;
    int lane = threadIdx.x & 31;
    if (o >= NOUT) return;
    const float* h = H + (size_t)(b * TT + TT - 1) * DD;
    float acc = 0.f;
    for (int i = lane; i < DD; i += 32)
        acc += h[i] * Wout[i * NOUT + o];
    #pragma unroll
    for (int s = 16; s > 0; s >>= 1)
        acc += __shfl_down_sync(0xffffffffu, acc, s);
    if (lane == 0) out[b * NOUT + o] = acc + bout[o];
}

// ---------------------------------------------------------------------------
// Launch
// ---------------------------------------------------------------------------
extern "C" void kernel_launch(void* const* d_in, const int* in_sizes, int n_in,
                              void* d_out, int out_size)
{
    (void)in_sizes; (void)n_in; (void)out_size;

    const float* X      = (const float*)d_in[0];
    const float* V_Adap = (const float*)d_in[1];
    const float* Wl     = (const float*)d_in[2];
    const float* bl     = (const float*)d_in[3];
    const float* Wr     = (const float*)d_in[4];
    const float* br     = (const float*)d_in[5];
    const float* att    = (const float*)d_in[6];
    const float* gbias  = (const float*)d_in[7];
    const float* Wfc    = (const float*)d_in[8];
    const float* bfc    = (const float*)d_in[9];
    const float* Wq     = (const float*)d_in[10];
    const float* bq     = (const float*)d_in[11];
    const float* Wk     = (const float*)d_in[12];
    const float* bk     = (const float*)d_in[13];
    const float* Wv     = (const float*)d_in[14];
    const float* bv     = (const float*)d_in[15];
    const float* Wo     = (const float*)d_in[16];
    const float* bo     = (const float*)d_in[17];
    const float* ln1g   = (const float*)d_in[18];
    const float* ln1b   = (const float*)d_in[19];
    const float* W1     = (const float*)d_in[20];
    const float* b1     = (const float*)d_in[21];
    const float* W2     = (const float*)d_in[22];
    const float* b2     = (const float*)d_in[23];
    const float* ln2g   = (const float*)d_in[24];
    const float* ln2b   = (const float*)d_in[25];
    const float* Wout   = (const float*)d_in[26];
    const float* bout   = (const float*)d_in[27];
    const int*   cls    = (const int*)d_in[28];

    float* base = nullptr;
    unsigned char* maskp = nullptr;
    __nv_bfloat16 *wth = nullptr, *wtl = nullptr, *ah = nullptr, *al = nullptr;
    __nv_bfloat16 *bh = nullptr, *blo = nullptr;
    cudaGetSymbolAddress((void**)&base,  g_scratch);
    cudaGetSymbolAddress((void**)&maskp, g_mask);
    cudaGetSymbolAddress((void**)&wth,   g_wt_hi);
    cudaGetSymbolAddress((void**)&wtl,   g_wt_lo);
    cudaGetSymbolAddress((void**)&ah,    g_a_hi);
    cudaGetSymbolAddress((void**)&al,    g_a_lo);
    cudaGetSymbolAddress((void**)&bh,    g_b_hi);
    cudaGetSymbolAddress((void**)&blo,   g_b_lo);

    float* h  = base + 0ull * DSZ;
    float* q  = base + 1ull * DSZ;
    float* k  = base + 2ull * DSZ;
    float* v  = base + 3ull * DSZ;
    float* t  = base + 6ull * DSZ;

    cudaFuncSetAttribute(gat_kernel,      cudaFuncAttributeMaxDynamicSharedMemorySize, GAT_SMEM_BYTES);
    cudaFuncSetAttribute(attn_kernel,     cudaFuncAttributeMaxDynamicSharedMemorySize, ATTN_SMEM_BYTES);
    cudaFuncSetAttribute(gemm_mma_kernel, cudaFuncAttributeMaxDynamicSharedMemorySize, GEMM_SMEM);

    mask_kernel<<<NN, NN>>>(V_Adap, cls, maskp);
    gat_kernel<<<ROWS, 256, GAT_SMEM_BYTES>>>(X, Wl, bl, Wr, br, att, gbias, Wfc, bfc, maskp,
                                              h, ah, al);

    // pre-transpose + split all 12 weight matrices in ONE launch
    {
        TsplitArgs ta;
        for (int l = 0; l < LAYERS; l++) {
            ta.w[l * 6 + 0] = Wq + (size_t)l * DSZ;
            ta.w[l * 6 + 1] = Wk + (size_t)l * DSZ;
            ta.w[l * 6 + 2] = Wv + (size_t)l * DSZ;
            ta.w[l * 6 + 3] = Wo + (size_t)l * DSZ;
            ta.w[l * 6 + 4] = W1 + (size_t)l * DSZ;
            ta.w[l * 6 + 5] = W2 + (size_t)l * DSZ;
        }
        dim3 tg(64, 64, 12);
        tsplit_all_kernel<<<tg, 256>>>(ta, wth, wtl);
    }

    dim3 gg(16, 16);
    for (int l = 0; l < LAYERS; l++) {
        size_t s0 = (size_t)(l * 6 + 0) * DSZ;
        size_t s1 = (size_t)(l * 6 + 1) * DSZ;
        size_t s2 = (size_t)(l * 6 + 2) * DSZ;
        size_t s3 = (size_t)(l * 6 + 3) * DSZ;
        size_t s4 = (size_t)(l * 6 + 4) * DSZ;
        size_t s5 = (size_t)(l * 6 + 5) * DSZ;

        gemm_mma_kernel<<<gg, GEMM_THREADS, GEMM_SMEM>>>(ah, al, wth + s0, wtl + s0, bq + l * DD,
                                                nullptr, q, nullptr, nullptr, 0);
        gemm_mma_kernel<<<gg, GEMM_THREADS, GEMM_SMEM>>>(ah, al, wth + s1, wtl + s1, bk + l * DD,
                                                nullptr, k, nullptr, nullptr, 0);
        gemm_mma_kernel<<<gg, GEMM_THREADS, GEMM_SMEM>>>(ah, al, wth + s2, wtl + s2, bv + l * DD,
                                                nullptr, v, nullptr, nullptr, 0);
        attn_kernel<<<BB * NHEADS, 256, ATTN_SMEM_BYTES>>>(q, k, v, ah, al);
        gemm_mma_kernel<<<gg, GEMM_THREADS, GEMM_SMEM>>>(ah, al, wth + s3, wtl + s3, bo + l * DD,
                                                h, t, nullptr, nullptr, 2);
        ln_kernel<<<ROWS, 256>>>(t, h, ln1g + l * DD, ln1b + l * DD, ah, al);
        gemm_mma_kernel<<<gg, GEMM_THREADS, GEMM_SMEM>>>(ah, al, wth + s4, wtl + s4, b1 + l * DFF,
                                                nullptr, nullptr, bh, blo, 3);
        gemm_mma_kernel<<<gg, GEMM_THREADS, GEMM_SMEM>>>(bh, blo, wth + s5, wtl + s5, b2 + l * DD,
                                                h, t, nullptr, nullptr, 2);
        ln_kernel<<<ROWS, 256>>>(t, h, ln2g + l * DD, ln2b + l * DD, ah, al);
    }

    out_kernel<<<BB, 320>>>(h, Wout, bout, (float*)d_out);
}

// round 13
// speedup vs baseline: 1.1270x; 1.0663x over previous
#include <cuda_runtime.h>
#include <cuda_fp16.h>
#include <math.h>
#include <stdint.h>

// ---------------------------------------------------------------------------
// Shapes
// ---------------------------------------------------------------------------
#define BB     32
#define TT     64
#define NN     128
#define F_IN   16
#define SOUT   16
#define DD     2048
#define NHEADS 16
#define DH     128
#define DFF    2048
#define LAYERS 2
#define NOUT   10
#define ROWS   (BB*TT)
#define DSZ    (ROWS*DD)        // 4M elements; one 2048x2048 matrix

// ---------------------------------------------------------------------------
// Static scratch (allocation-free rule)
// ---------------------------------------------------------------------------
__device__ float g_scratch[7ull * DSZ];                 // h,q,k,v,-,-,tmp
__device__ unsigned char g_mask[NN * NN];
__device__ __half g_wt[12ull * DSZ];                    // transposed weights fp16
__device__ __half g_a[DSZ];                             // activation fp16 (A)
__device__ __half g_b[DSZ];                             // activation fp16 (B, FFN mid)

// ---------------------------------------------------------------------------
// Helpers
// ---------------------------------------------------------------------------
__device__ __forceinline__ uint32_t smem_u32(const void* p) {
    uint32_t a;
    asm("{ .reg .u64 t; cvta.to.shared.u64 t, %1; cvt.u32.u64 %0, t; }" : "=r"(a) : "l"(p));
    return a;
}

#define CP_ASYNC16(saddr, gptr) \
    asm volatile("cp.async.cg.shared.global [%0], [%1], 16;" :: "r"(saddr), "l"(gptr) : "memory")
#define CP_COMMIT()  asm volatile("cp.async.commit_group;" ::: "memory")
#define CP_WAIT0()   asm volatile("cp.async.wait_group 0;" ::: "memory")

__device__ __forceinline__ void ldsm_x4(uint32_t* r, uint32_t addr) {
    asm volatile("ldmatrix.sync.aligned.m8n8.x4.shared.b16 {%0,%1,%2,%3}, [%4];"
                 : "=r"(r[0]), "=r"(r[1]), "=r"(r[2]), "=r"(r[3]) : "r"(addr));
}
__device__ __forceinline__ void mma_fp16(float* d, const uint32_t* a, const uint32_t* b) {
    asm volatile(
        "mma.sync.aligned.m16n8k16.row.col.f32.f16.f16.f32 "
        "{%0,%1,%2,%3}, {%4,%5,%6,%7}, {%8,%9}, {%0,%1,%2,%3};"
        : "+f"(d[0]), "+f"(d[1]), "+f"(d[2]), "+f"(d[3])
        : "r"(a[0]), "r"(a[1]), "r"(a[2]), "r"(a[3]), "r"(b[0]), "r"(b[1]));
}

// ---------------------------------------------------------------------------
// Mask kernel
// ---------------------------------------------------------------------------
__global__ void mask_kernel(const float* __restrict__ V, const int* __restrict__ cls,
                            unsigned char* __restrict__ mask)
{
    int i = blockIdx.x, j = threadIdx.x;
    int c = *cls;
    float v = V[(size_t)c * NN * NN + i * NN + j];
    float a = (1.0f / (1.0f + expf(-v))) * (1.0f / (float)NN);
    mask[i * NN + j] = (a > 0.004f) || (i == j);
}

// ---------------------------------------------------------------------------
// GAT stage — register-tiled; emits h fp32 + fp16
// ---------------------------------------------------------------------------
#define GAT_SMEM_FLOATS (2048+1024+1024+1024+64+64+64+64+16+8320+8320+16384)
#define GAT_SMEM_BYTES  (GAT_SMEM_FLOATS*4 + NN*NN)

__global__ __launch_bounds__(256) void gat_kernel(
    const float* __restrict__ X,
    const float* __restrict__ Wl, const float* __restrict__ bl,
    const float* __restrict__ Wr, const float* __restrict__ br,
    const float* __restrict__ att, const float* __restrict__ gbias,
    const float* __restrict__ Wfc, const float* __restrict__ bfc,
    const unsigned char* __restrict__ gmask,
    float* __restrict__ H, __half* __restrict__ Hf)
{
    extern __shared__ float sm[];
    float* s_x   = sm;
    float* s_wl  = s_x   + 2048;
    float* s_wr  = s_wl  + 1024;
    float* s_wfc = s_wr  + 1024;
    float* s_att = s_wfc + 1024;
    float* s_bl  = s_att + 64;
    float* s_br  = s_bl  + 64;
    float* s_gb  = s_br  + 64;
    float* s_bfc = s_gb  + 64;
    float* s_xl  = s_bfc + 16;          // 128*65
    float* s_xr  = s_xl  + 8320;        // 128*65 ; reused as "out"
    float* s_e   = s_xr  + 8320;        // 128*128
    unsigned char* s_mask = (unsigned char*)(s_e + 16384);

    const int tid = threadIdx.x;
    const int r   = blockIdx.x;
    const float* xg = X + (size_t)r * (NN * F_IN);

    for (int i = tid; i < 2048; i += 256) s_x[i] = xg[i];
    for (int i = tid; i < 1024; i += 256) { s_wl[i] = Wl[i]; s_wr[i] = Wr[i]; s_wfc[i] = Wfc[i]; }
    if (tid < 64) { s_att[tid] = att[tid]; s_bl[tid] = bl[tid]; s_br[tid] = br[tid]; s_gb[tid] = gbias[tid]; }
    if (tid < 16) s_bfc[tid] = bfc[tid];
    for (int i = tid * 4; i < NN * NN; i += 256 * 4)
        *(uint32_t*)(s_mask + i) = *(const uint32_t*)(gmask + i);
    __syncthreads();

    for (int idx = tid; idx < 8192; idx += 256) {
        int i = idx >> 6, h = idx & 63;
        const float* xi = s_x + i * 16;
        float a = s_bl[h], b = s_br[h];
        #pragma unroll
        for (int f = 0; f < 16; f++) {
            float xv = xi[f];
            a += xv * s_wl[f * 64 + h];
            b += xv * s_wr[f * 64 + h];
        }
        s_xl[i * 65 + h] = a;
        s_xr[i * 65 + h] = b;
    }
    __syncthreads();

    // e[i][j] — 8x8 per-thread register tile
    {
        const int ib = tid >> 4;
        const int jb = tid & 15;
        float acc[8][8];
        #pragma unroll
        for (int a = 0; a < 8; a++)
            #pragma unroll
            for (int b = 0; b < 8; b++) acc[a][b] = 0.f;

        for (int h = 0; h < 64; h++) {
            float av = s_att[h];
            float xls[8], xrs[8];
            #pragma unroll
            for (int u = 0; u < 8; u++) xls[u] = s_xl[(ib + u * 16) * 65 + h];
            #pragma unroll
            for (int u = 0; u < 8; u++) xrs[u] = s_xr[(jb + u * 16) * 65 + h];
            #pragma unroll
            for (int ii = 0; ii < 8; ii++)
                #pragma unroll
                for (int jj = 0; jj < 8; jj++) {
                    float v = xls[ii] + xrs[jj];
                    v = (v > 0.f) ? v : 0.2f * v;
                    acc[ii][jj] = fmaf(av, v, acc[ii][jj]);
                }
        }
        #pragma unroll
        for (int ii = 0; ii < 8; ii++) {
            int i = ib + ii * 16;
            #pragma unroll
            for (int jj = 0; jj < 8; jj++) {
                int j = jb + jj * 16;
                s_e[i * 128 + j] = s_mask[i * 128 + j] ? acc[ii][jj] : -1e9f;
            }
        }
    }
    __syncthreads();

    if (tid < 128) {
        int j = tid;
        float m = -1e30f;
        for (int i = 0; i < 128; i++) m = fmaxf(m, s_e[i * 128 + j]);
        float s = 0.f;
        for (int i = 0; i < 128; i++) {
            float ev = __expf(s_e[i * 128 + j] - m);
            s_e[i * 128 + j] = ev;
            s += ev;
        }
        float inv = 1.0f / s;
        for (int i = 0; i < 128; i++) s_e[i * 128 + j] *= inv;
    }
    __syncthreads();

    // out[j][h] -> s_xr
    {
        const int hb = (tid & 15) * 4;
        const int jb = tid >> 4;
        float acc[8][4];
        #pragma unroll
        for (int a = 0; a < 8; a++)
            #pragma unroll
            for (int b = 0; b < 4; b++) acc[a][b] = 0.f;

        for (int i = 0; i < 128; i++) {
            float xv[4];
            #pragma unroll
            for (int u = 0; u < 4; u++) xv[u] = s_xl[i * 65 + hb + u];
            #pragma unroll
            for (int jj = 0; jj < 8; jj++) {
                float a = s_e[i * 128 + jb + jj * 16];
                #pragma unroll
                for (int u = 0; u < 4; u++)
                    acc[jj][u] = fmaf(a, xv[u], acc[jj][u]);
            }
        }
        __syncthreads();
        #pragma unroll
        for (int jj = 0; jj < 8; jj++) {
            int j = jb + jj * 16;
            #pragma unroll
            for (int u = 0; u < 4; u++)
                s_xr[j * 65 + hb + u] = acc[jj][u] + s_gb[hb + u];
        }
    }
    __syncthreads();

    // y = out @ Wfc + bfc -> H fp32 + fp16
    {
        const int j  = tid >> 1;
        const int s0 = (tid & 1) * 8;
        float acc[8];
        #pragma unroll
        for (int u = 0; u < 8; u++) acc[u] = s_bfc[s0 + u];
        const float* oj = s_xr + j * 65;
        for (int h = 0; h < 64; h++) {
            float ov = oj[h];
            const float4 w0 = *(const float4*)&s_wfc[h * 16 + s0];
            const float4 w1 = *(const float4*)&s_wfc[h * 16 + s0 + 4];
            acc[0] = fmaf(ov, w0.x, acc[0]); acc[1] = fmaf(ov, w0.y, acc[1]);
            acc[2] = fmaf(ov, w0.z, acc[2]); acc[3] = fmaf(ov, w0.w, acc[3]);
            acc[4] = fmaf(ov, w1.x, acc[4]); acc[5] = fmaf(ov, w1.y, acc[5]);
            acc[6] = fmaf(ov, w1.z, acc[6]); acc[7] = fmaf(ov, w1.w, acc[7]);
        }
        size_t base = (size_t)r * DD + j * 16 + s0;
        #pragma unroll
        for (int u = 0; u < 8; u++) H[base + u] = acc[u];
        #pragma unroll
        for (int u = 0; u < 8; u++) Hf[base + u] = __float2half(acc[u]);
    }
}

// ---------------------------------------------------------------------------
// Weight transpose to fp16 — all 12 matrices in one launch (z = slot)
// ---------------------------------------------------------------------------
struct TsplitArgs { const float* w[12]; };

__global__ __launch_bounds__(256) void tsplit_all_kernel(
    TsplitArgs args, __half* __restrict__ TBase)
{
    __shared__ float t[32][33];
    const int slot = blockIdx.z;
    const float* W = args.w[slot];
    __half* T = TBase + (size_t)slot * DSZ;

    const int bx = blockIdx.x, by = blockIdx.y;
    const int tx = threadIdx.x & 31, ty = threadIdx.x >> 5;
    #pragma unroll
    for (int i = 0; i < 4; i++) {
        int k = by * 32 + ty + i * 8;
        t[ty + i * 8][tx] = W[(size_t)k * 2048 + bx * 32 + tx];
    }
    __syncthreads();
    #pragma unroll
    for (int i = 0; i < 4; i++) {
        int n = bx * 32 + ty + i * 8;
        int k = by * 32 + tx;
        T[(size_t)n * 2048 + k] = __float2half(t[tx][ty + i * 8]);
    }
}

// ---------------------------------------------------------------------------
// fp16 GEMM via mma.sync — 512 threads, 16 warps, warp tile 32x32,
// BK=64, 2-stage cp.async pipeline.
//   mode 0: C = acc+bias | 2: +resid | 3: relu -> fp16 (Of)
// ---------------------------------------------------------------------------
#define GEMM_THREADS   512
#define GEMM_BK        64
#define GEMM_LDS       72                       // padded row (elements)
#define GEMM_ARR_BYTES (128*GEMM_LDS*2)         // 18432
#define GEMM_STAGE     (2*GEMM_ARR_BYTES)       // 36864
#define GEMM_SMEM      (2*GEMM_STAGE)           // 73728

__device__ __forceinline__ void gemm_load_stage(
    const __half* A, const __half* B,
    uint32_t sbase, int buf, int m0, int n0, int kc, int tid)
{
    uint32_t sb = sbase + buf * GEMM_STAGE;
    const char* ga = (const char*)(A + (size_t)m0 * 2048 + kc);
    const char* gb = (const char*)(B + (size_t)n0 * 2048 + kc);
    // full coverage: 128 rows x 128 bytes = 1024 x 16B chunks per array,
    // 512 threads -> 2 chunks per thread per array
    #pragma unroll
    for (int j = 0; j < 2; j++) {
        int idx = tid + j * 512;           // 0..1023
        int row = idx >> 3;                // 0..127
        int cu  = idx & 7;                 // 8 x 16B = 128B per row
        uint32_t soff = row * (GEMM_LDS * 2) + cu * 16;
        size_t  goff = (size_t)row * 4096 + cu * 16;
        CP_ASYNC16(sb + soff, ga + goff);
        CP_ASYNC16(sb + GEMM_ARR_BYTES + soff, gb + goff);
    }
}

__global__ __launch_bounds__(GEMM_THREADS, 1)
void gemm_mma_kernel(
    const __half* __restrict__ A, const __half* __restrict__ B,
    const float* __restrict__ bias, const float* __restrict__ resid,
    float* __restrict__ C, __half* __restrict__ Of,
    int mode)
{
    extern __shared__ char dsm[];
    const uint32_t sbase = smem_u32(dsm);

    const int tid  = threadIdx.x;
    const int wid  = tid >> 5;
    const int lane = tid & 31;
    const int wm   = wid & 3;          // m offset 32*wm
    const int wn   = wid >> 2;         // n offset 32*wn
    const int m0   = blockIdx.y * 128;
    const int n0   = blockIdx.x * 128;

    const int aoff = (wm * 32 + (lane & 15)) * GEMM_LDS + (lane >> 4) * 8;
    const int boff = (wn * 32 + (lane >> 4) * 8 + (lane & 7)) * GEMM_LDS + ((lane >> 3) & 1) * 8;

    float acc[2][4][4];
    #pragma unroll
    for (int mt = 0; mt < 2; mt++)
        #pragma unroll
        for (int nt = 0; nt < 4; nt++)
            #pragma unroll
            for (int c = 0; c < 4; c++) acc[mt][nt][c] = 0.f;

    gemm_load_stage(A, B, sbase, 0, m0, n0, 0, tid);
    CP_COMMIT();
    CP_WAIT0();
    __syncthreads();

    const int NCHUNK = 2048 / GEMM_BK;   // 32
    for (int i = 0; i < NCHUNK; i++) {
        const int buf = i & 1;
        if (i + 1 < NCHUNK) {
            gemm_load_stage(A, B, sbase, buf ^ 1, m0, n0, (i + 1) * GEMM_BK, tid);
            CP_COMMIT();
        }

        const uint32_t aB = sbase + buf * GEMM_STAGE;
        const uint32_t bB = aB + GEMM_ARR_BYTES;

        #pragma unroll
        for (int kt = 0; kt < 4; kt++) {
            uint32_t af[2][4];
            #pragma unroll
            for (int mt = 0; mt < 2; mt++) {
                uint32_t ao = (aoff + mt * 16 * GEMM_LDS + kt * 16) * 2;
                ldsm_x4(af[mt], aB + ao);
            }
            #pragma unroll
            for (int np = 0; np < 2; np++) {
                uint32_t bo = (boff + np * 16 * GEMM_LDS + kt * 16) * 2;
                uint32_t bf[4];
                ldsm_x4(bf, bB + bo);
                #pragma unroll
                for (int half = 0; half < 2; half++) {
                    int nt = np * 2 + half;
                    #pragma unroll
                    for (int mt = 0; mt < 2; mt++)
                        mma_fp16(acc[mt][nt], af[mt], bf + half * 2);
                }
            }
        }

        CP_WAIT0();
        __syncthreads();
    }

    // epilogue
    const int g  = lane >> 2;
    const int t2 = lane & 3;
    #pragma unroll
    for (int mt = 0; mt < 2; mt++) {
        #pragma unroll
        for (int nt = 0; nt < 4; nt++) {
            int row = m0 + wm * 32 + mt * 16 + g;
            int col = n0 + wn * 32 + nt * 8 + t2 * 2;
            float b0 = __ldg(bias + col), b1 = __ldg(bias + col + 1);
            #pragma unroll
            for (int half = 0; half < 2; half++) {
                int rr = row + half * 8;
                float v0 = acc[mt][nt][half * 2 + 0] + b0;
                float v1 = acc[mt][nt][half * 2 + 1] + b1;
                size_t off = (size_t)rr * 2048 + col;
                if (mode == 3) {
                    v0 = fmaxf(v0, 0.f); v1 = fmaxf(v1, 0.f);
                    __half2 hp; hp.x = __float2half(v0); hp.y = __float2half(v1);
                    *(uint32_t*)(Of + off) = *(uint32_t*)&hp;
                } else {
                    if (mode == 2) {
                        const float2 rp = *(const float2*)(resid + off);
                        v0 += rp.x; v1 += rp.y;
                    }
                    float2 o; o.x = v0; o.y = v1;
                    *(float2*)(C + off) = o;
                }
            }
        }
    }
}

// ---------------------------------------------------------------------------
// Attention: writes fp16 ao directly
// ---------------------------------------------------------------------------
#define ATTN_SMEM_BYTES ((8192 + 8256 + 8192 + 4160) * 4)

__global__ __launch_bounds__(256) void attn_kernel(
    const float* __restrict__ Q, const float* __restrict__ K,
    const float* __restrict__ V, __half* __restrict__ AOf)
{
    extern __shared__ float sm[];
    float* sq = sm;
    float* sk = sq + 8192;
    float* sv = sk + 8256;
    float* sc = sv + 8192;

    const int tid = threadIdx.x;
    const int b   = blockIdx.x >> 4;
    const int hd  = blockIdx.x & 15;
    const size_t base = (size_t)(b * TT) * DD + hd * DH;
    const float SCALE = 0.08838834764831845f;

    for (int idx = tid; idx < 8192; idx += 256) {
        int t = idx >> 7, d = idx & 127;
        size_t g = base + (size_t)t * DD + d;
        sq[idx]          = Q[g] * SCALE;
        sk[t * 129 + d]  = K[g];
        sv[idx]          = V[g];
    }
    __syncthreads();

    for (int idx = tid; idx < 4096; idx += 256) {
        int t1 = idx >> 6, t2 = idx & 63;
        const float* qp = sq + t1 * 128;
        const float* kp = sk + t2 * 129;
        float acc = 0.f;
        #pragma unroll 16
        for (int d = 0; d < 128; d++) acc += qp[d] * kp[d];
        sc[t1 * 65 + t2] = acc;
    }
    __syncthreads();

    if (tid < 64) {
        float* rowp = sc + tid * 65;
        float m = -1e30f;
        for (int i = 0; i < 64; i++) m = fmaxf(m, rowp[i]);
        float s = 0.f;
        for (int i = 0; i < 64; i++) { float e = __expf(rowp[i] - m); rowp[i] = e; s += e; }
        float inv = 1.0f / s;
        for (int i = 0; i < 64; i++) rowp[i] *= inv;
    }
    __syncthreads();

    for (int idx = tid; idx < 8192; idx += 256) {
        int t = idx >> 7, d = idx & 127;
        const float* a = sc + t * 65;
        float acc = 0.f;
        #pragma unroll 16
        for (int t2 = 0; t2 < 64; t2++) acc += a[t2] * sv[t2 * 128 + d];
        AOf[base + (size_t)t * DD + d] = __float2half(acc);
    }
}

// ---------------------------------------------------------------------------
// LayerNorm: fp32 out + fp16 out
// ---------------------------------------------------------------------------
__global__ __launch_bounds__(256) void ln_kernel(
    const float* __restrict__ x, float* __restrict__ y,
    const float* __restrict__ g, const float* __restrict__ b,
    __half* __restrict__ Yf)
{
    __shared__ float red[256];
    const int row = blockIdx.x, tid = threadIdx.x;
    const float* xr = x + (size_t)row * DD;

    float s = 0.f;
    for (int i = tid; i < DD; i += 256) s += xr[i];
    red[tid] = s; __syncthreads();
    for (int st = 128; st > 0; st >>= 1) { if (tid < st) red[tid] += red[tid + st]; __syncthreads(); }
    float mu = red[0] * (1.0f / DD);
    __syncthreads();

    float v = 0.f;
    for (int i = tid; i < DD; i += 256) { float d = xr[i] - mu; v += d * d; }
    red[tid] = v; __syncthreads();
    for (int st = 128; st > 0; st >>= 1) { if (tid < st) red[tid] += red[tid + st]; __syncthreads(); }
    float var = red[0] * (1.0f / DD);
    float inv = 1.0f / sqrtf(var + 1e-5f);

    float* yr = y + (size_t)row * DD;
    __half* fr = Yf + (size_t)row * DD;
    for (int i = tid; i < DD; i += 256) {
        float val = (xr[i] - mu) * inv * g[i] + b[i];
        yr[i] = val;
        fr[i] = __float2half(val);
    }
}

// ---------------------------------------------------------------------------
// Final projection
// ---------------------------------------------------------------------------
__global__ void out_kernel(const float* __restrict__ H, const float* __restrict__ Wout,
                           const float* __restrict__ bout, float* __restrict__ out)
{
    int b = blockIdx.x;
    int o = threadIdx.x >> 5;
    int lane = threadIdx.x & 31;
    if (o >= NOUT) return;
    const float* h = H + (size_t)(b * TT + TT - 1) * DD;
    float acc = 0.f;
    for (int i = lane; i < DD; i += 32)
        acc += h[i] * Wout[i * NOUT + o];
    #pragma unroll
    for (int s = 16; s > 0; s >>= 1)
        acc += __shfl_down_sync(0xffffffffu, acc, s);
    if (lane == 0) out[b * NOUT + o] = acc + bout[o];
}

// ---------------------------------------------------------------------------
// Launch
// ---------------------------------------------------------------------------
extern "C" void kernel_launch(void* const* d_in, const int* in_sizes, int n_in,
                              void* d_out, int out_size)
{
    (void)in_sizes; (void)n_in; (void)out_size;

    const float* X      = (const float*)d_in[0];
    const float* V_Adap = (const float*)d_in[1];
    const float* Wl     = (const float*)d_in[2];
    const float* bl     = (const float*)d_in[3];
    const float* Wr     = (const float*)d_in[4];
    const float* br     = (const float*)d_in[5];
    const float* att    = (const float*)d_in[6];
    const float* gbias  = (const float*)d_in[7];
    const float* Wfc    = (const float*)d_in[8];
    const float* bfc    = (const float*)d_in[9];
    const float* Wq     = (const float*)d_in[10];
    const float* bq     = (const float*)d_in[11];
    const float* Wk     = (const float*)d_in[12];
    const float* bk     = (const float*)d_in[13];
    const float* Wv     = (const float*)d_in[14];
    const float* bv     = (const float*)d_in[15];
    const float* Wo     = (const float*)d_in[16];
    const float* bo     = (const float*)d_in[17];
    const float* ln1g   = (const float*)d_in[18];
    const float* ln1b   = (const float*)d_in[19];
    const float* W1     = (const float*)d_in[20];
    const float* b1     = (const float*)d_in[21];
    const float* W2     = (const float*)d_in[22];
    const float* b2     = (const float*)d_in[23];
    const float* ln2g   = (const float*)d_in[24];
    const float* ln2b   = (const float*)d_in[25];
    const float* Wout   = (const float*)d_in[26];
    const float* bout   = (const float*)d_in[27];
    const int*   cls    = (const int*)d_in[28];

    float* base = nullptr;
    unsigned char* maskp = nullptr;
    __half *wt = nullptr, *af = nullptr, *bf = nullptr;
    cudaGetSymbolAddress((void**)&base,  g_scratch);
    cudaGetSymbolAddress((void**)&maskp, g_mask);
    cudaGetSymbolAddress((void**)&wt,    g_wt);
    cudaGetSymbolAddress((void**)&af,    g_a);
    cudaGetSymbolAddress((void**)&bf,    g_b);

    float* h  = base + 0ull * DSZ;
    float* q  = base + 1ull * DSZ;
    float* k  = base + 2ull * DSZ;
    float* v  = base + 3ull * DSZ;
    float* t  = base + 6ull * DSZ;

    cudaFuncSetAttribute(gat_kernel,      cudaFuncAttributeMaxDynamicSharedMemorySize, GAT_SMEM_BYTES);
    cudaFuncSetAttribute(attn_kernel,     cudaFuncAttributeMaxDynamicSharedMemorySize, ATTN_SMEM_BYTES);
    cudaFuncSetAttribute(gemm_mma_kernel, cudaFuncAttributeMaxDynamicSharedMemorySize, GEMM_SMEM);

    mask_kernel<<<NN, NN>>>(V_Adap, cls, maskp);
    gat_kernel<<<ROWS, 256, GAT_SMEM_BYTES>>>(X, Wl, bl, Wr, br, att, gbias, Wfc, bfc, maskp,
                                              h, af);

    // transpose all 12 weight matrices to fp16 in ONE launch
    {
        TsplitArgs ta;
        for (int l = 0; l < LAYERS; l++) {
            ta.w[l * 6 + 0] = Wq + (size_t)l * DSZ;
            ta.w[l * 6 + 1] = Wk + (size_t)l * DSZ;
            ta.w[l * 6 + 2] = Wv + (size_t)l * DSZ;
            ta.w[l * 6 + 3] = Wo + (size_t)l * DSZ;
            ta.w[l * 6 + 4] = W1 + (size_t)l * DSZ;
            ta.w[l * 6 + 5] = W2 + (size_t)l * DSZ;
        }
        dim3 tg(64, 64, 12);
        tsplit_all_kernel<<<tg, 256>>>(ta, wt);
    }

    dim3 gg(16, 16);
    for (int l = 0; l < LAYERS; l++) {
        __half* w0  = wt + (size_t)(l * 6 + 0) * DSZ;
        __half* w1p = wt + (size_t)(l * 6 + 1) * DSZ;
        __half* w2p = wt + (size_t)(l * 6 + 2) * DSZ;
        __half* w3  = wt + (size_t)(l * 6 + 3) * DSZ;
        __half* w4  = wt + (size_t)(l * 6 + 4) * DSZ;
        __half* w5  = wt + (size_t)(l * 6 + 5) * DSZ;

        gemm_mma_kernel<<<gg, GEMM_THREADS, GEMM_SMEM>>>(af, w0, bq + l * DD,
                                                nullptr, q, nullptr, 0);
        gemm_mma_kernel<<<gg, GEMM_THREADS, GEMM_SMEM>>>(af, w1p, bk + l * DD,
                                                nullptr, k, nullptr, 0);
        gemm_mma_kernel<<<gg, GEMM_THREADS, GEMM_SMEM>>>(af, w2p, bv + l * DD,
                                                nullptr, v, nullptr, 0);
        attn_kernel<<<BB * NHEADS, 256, ATTN_SMEM_BYTES>>>(q, k, v, af);
        gemm_mma_kernel<<<gg, GEMM_THREADS, GEMM_SMEM>>>(af, w3, bo + l * DD,
                                                h, t, nullptr, 2);
        ln_kernel<<<ROWS, 256>>>(t, h, ln1g + l * DD, ln1b + l * DD, af);
        gemm_mma_kernel<<<gg, GEMM_THREADS, GEMM_SMEM>>>(af, w4, b1 + l * DFF,
                                                nullptr, nullptr, bf, 3);
        gemm_mma_kernel<<<gg, GEMM_THREADS, GEMM_SMEM>>>(bf, w5, b2 + l * DD,
                                                h, t, nullptr, 2);
        ln_kernel<<<ROWS, 256>>>(t, h, ln2g + l * DD, ln2b + l * DD, af);
    }

    out_kernel<<<BB, 320>>>(h, Wout, bout, (float*)d_out);
}

// round 14
// speedup vs baseline: 1.8321x; 1.6257x over previous
#include <cuda_runtime.h>
#include <cuda_fp16.h>
#include <math.h>
#include <stdint.h>

// ---------------------------------------------------------------------------
// Shapes
// ---------------------------------------------------------------------------
#define BB     32
#define TT     64
#define NN     128
#define F_IN   16
#define SOUT   16
#define DD     2048
#define NHEADS 16
#define DH     128
#define DFF    2048
#define LAYERS 2
#define NOUT   10
#define ROWS   (BB*TT)
#define DSZ    (ROWS*DD)        // 4M elements; one 2048x2048 matrix

// ---------------------------------------------------------------------------
// Static scratch (allocation-free rule)
// ---------------------------------------------------------------------------
__device__ float g_scratch[7ull * DSZ];                 // h,-,-,-,-,-,tmp (+qkv fp16 in slots 1-2)
__device__ unsigned char g_mask[NN * NN];
__device__ __half g_wt[12ull * DSZ];                    // transposed weights fp16
__device__ __half g_a[DSZ];                             // activation fp16 (A)
__device__ __half g_b[DSZ];                             // activation fp16 (B, FFN mid)

// ---------------------------------------------------------------------------
// Helpers
// ---------------------------------------------------------------------------
__device__ __forceinline__ uint32_t smem_u32(const void* p) {
    uint32_t a;
    asm("{ .reg .u64 t; cvta.to.shared.u64 t, %1; cvt.u32.u64 %0, t; }" : "=r"(a) : "l"(p));
    return a;
}

#define CP_ASYNC16(saddr, gptr) \
    asm volatile("cp.async.cg.shared.global [%0], [%1], 16;" :: "r"(saddr), "l"(gptr) : "memory")
#define CP_COMMIT()  asm volatile("cp.async.commit_group;" ::: "memory")
#define CP_WAIT0()   asm volatile("cp.async.wait_group 0;" ::: "memory")

__device__ __forceinline__ void ldsm_x4(uint32_t* r, uint32_t addr) {
    asm volatile("ldmatrix.sync.aligned.m8n8.x4.shared.b16 {%0,%1,%2,%3}, [%4];"
                 : "=r"(r[0]), "=r"(r[1]), "=r"(r[2]), "=r"(r[3]) : "r"(addr));
}
__device__ __forceinline__ void mma_fp16(float* d, const uint32_t* a, const uint32_t* b) {
    asm volatile(
        "mma.sync.aligned.m16n8k16.row.col.f32.f16.f16.f32 "
        "{%0,%1,%2,%3}, {%4,%5,%6,%7}, {%8,%9}, {%0,%1,%2,%3};"
        : "+f"(d[0]), "+f"(d[1]), "+f"(d[2]), "+f"(d[3])
        : "r"(a[0]), "r"(a[1]), "r"(a[2]), "r"(a[3]), "r"(b[0]), "r"(b[1]));
}

// ---------------------------------------------------------------------------
// Mask kernel
// ---------------------------------------------------------------------------
__global__ void mask_kernel(const float* __restrict__ V, const int* __restrict__ cls,
                            unsigned char* __restrict__ mask)
{
    int i = blockIdx.x, j = threadIdx.x;
    int c = *cls;
    float v = V[(size_t)c * NN * NN + i * NN + j];
    float a = (1.0f / (1.0f + expf(-v))) * (1.0f / (float)NN);
    mask[i * NN + j] = (a > 0.004f) || (i == j);
}

// ---------------------------------------------------------------------------
// GAT stage — register-tiled; parallel softmax; emits h fp32 + fp16
// ---------------------------------------------------------------------------
#define GAT_SMEM_FLOATS (2048+1024+1024+1024+64+64+64+64+16+8320+8320+16384)
#define GAT_SMEM_BYTES  (GAT_SMEM_FLOATS*4 + NN*NN)

__global__ __launch_bounds__(256) void gat_kernel(
    const float* __restrict__ X,
    const float* __restrict__ Wl, const float* __restrict__ bl,
    const float* __restrict__ Wr, const float* __restrict__ br,
    const float* __restrict__ att, const float* __restrict__ gbias,
    const float* __restrict__ Wfc, const float* __restrict__ bfc,
    const unsigned char* __restrict__ gmask,
    float* __restrict__ H, __half* __restrict__ Hf)
{
    extern __shared__ float sm[];
    float* s_x   = sm;
    float* s_wl  = s_x   + 2048;
    float* s_wr  = s_wl  + 1024;
    float* s_wfc = s_wr  + 1024;
    float* s_att = s_wfc + 1024;
    float* s_bl  = s_att + 64;
    float* s_br  = s_bl  + 64;
    float* s_gb  = s_br  + 64;
    float* s_bfc = s_gb  + 64;
    float* s_xl  = s_bfc + 16;          // 128*65
    float* s_xr  = s_xl  + 8320;        // 128*65 ; reused as "out"
    float* s_e   = s_xr  + 8320;        // 128*128
    unsigned char* s_mask = (unsigned char*)(s_e + 16384);

    const int tid = threadIdx.x;
    const int r   = blockIdx.x;
    const float* xg = X + (size_t)r * (NN * F_IN);

    for (int i = tid; i < 2048; i += 256) s_x[i] = xg[i];
    for (int i = tid; i < 1024; i += 256) { s_wl[i] = Wl[i]; s_wr[i] = Wr[i]; s_wfc[i] = Wfc[i]; }
    if (tid < 64) { s_att[tid] = att[tid]; s_bl[tid] = bl[tid]; s_br[tid] = br[tid]; s_gb[tid] = gbias[tid]; }
    if (tid < 16) s_bfc[tid] = bfc[tid];
    for (int i = tid * 4; i < NN * NN; i += 256 * 4)
        *(uint32_t*)(s_mask + i) = *(const uint32_t*)(gmask + i);
    __syncthreads();

    for (int idx = tid; idx < 8192; idx += 256) {
        int i = idx >> 6, h = idx & 63;
        const float* xi = s_x + i * 16;
        float a = s_bl[h], b = s_br[h];
        #pragma unroll
        for (int f = 0; f < 16; f++) {
            float xv = xi[f];
            a += xv * s_wl[f * 64 + h];
            b += xv * s_wr[f * 64 + h];
        }
        s_xl[i * 65 + h] = a;
        s_xr[i * 65 + h] = b;
    }
    __syncthreads();

    // e[i][j] — 8x8 per-thread register tile
    {
        const int ib = tid >> 4;
        const int jb = tid & 15;
        float acc[8][8];
        #pragma unroll
        for (int a = 0; a < 8; a++)
            #pragma unroll
            for (int b = 0; b < 8; b++) acc[a][b] = 0.f;

        for (int h = 0; h < 64; h++) {
            float av = s_att[h];
            float xls[8], xrs[8];
            #pragma unroll
            for (int u = 0; u < 8; u++) xls[u] = s_xl[(ib + u * 16) * 65 + h];
            #pragma unroll
            for (int u = 0; u < 8; u++) xrs[u] = s_xr[(jb + u * 16) * 65 + h];
            #pragma unroll
            for (int ii = 0; ii < 8; ii++)
                #pragma unroll
                for (int jj = 0; jj < 8; jj++) {
                    float v = xls[ii] + xrs[jj];
                    v = (v > 0.f) ? v : 0.2f * v;
                    acc[ii][jj] = fmaf(av, v, acc[ii][jj]);
                }
        }
        #pragma unroll
        for (int ii = 0; ii < 8; ii++) {
            int i = ib + ii * 16;
            #pragma unroll
            for (int jj = 0; jj < 8; jj++) {
                int j = jb + jj * 16;
                s_e[i * 128 + j] = s_mask[i * 128 + j] ? acc[ii][jj] : -1e9f;
            }
        }
    }
    __syncthreads();

    // softmax over i per column j — 2 threads per column + shfl pair-reduce
    {
        const int j  = tid >> 1;
        const int hf = tid & 1;
        const int i0 = hf * 64;
        float m = -1e30f;
        for (int i = i0; i < i0 + 64; i++) m = fmaxf(m, s_e[i * 128 + j]);
        m = fmaxf(m, __shfl_xor_sync(0xffffffffu, m, 1));
        float s = 0.f;
        for (int i = i0; i < i0 + 64; i++) {
            float ev = __expf(s_e[i * 128 + j] - m);
            s_e[i * 128 + j] = ev;
            s += ev;
        }
        s += __shfl_xor_sync(0xffffffffu, s, 1);
        float inv = 1.0f / s;
        for (int i = i0; i < i0 + 64; i++) s_e[i * 128 + j] *= inv;
    }
    __syncthreads();

    // out[j][h] -> s_xr
    {
        const int hb = (tid & 15) * 4;
        const int jb = tid >> 4;
        float acc[8][4];
        #pragma unroll
        for (int a = 0; a < 8; a++)
            #pragma unroll
            for (int b = 0; b < 4; b++) acc[a][b] = 0.f;

        for (int i = 0; i < 128; i++) {
            float xv[4];
            #pragma unroll
            for (int u = 0; u < 4; u++) xv[u] = s_xl[i * 65 + hb + u];
            #pragma unroll
            for (int jj = 0; jj < 8; jj++) {
                float a = s_e[i * 128 + jb + jj * 16];
                #pragma unroll
                for (int u = 0; u < 4; u++)
                    acc[jj][u] = fmaf(a, xv[u], acc[jj][u]);
            }
        }
        __syncthreads();
        #pragma unroll
        for (int jj = 0; jj < 8; jj++) {
            int j = jb + jj * 16;
            #pragma unroll
            for (int u = 0; u < 4; u++)
                s_xr[j * 65 + hb + u] = acc[jj][u] + s_gb[hb + u];
        }
    }
    __syncthreads();

    // y = out @ Wfc + bfc -> H fp32 + fp16
    {
        const int j  = tid >> 1;
        const int s0 = (tid & 1) * 8;
        float acc[8];
        #pragma unroll
        for (int u = 0; u < 8; u++) acc[u] = s_bfc[s0 + u];
        const float* oj = s_xr + j * 65;
        for (int h = 0; h < 64; h++) {
            float ov = oj[h];
            const float4 w0 = *(const float4*)&s_wfc[h * 16 + s0];
            const float4 w1 = *(const float4*)&s_wfc[h * 16 + s0 + 4];
            acc[0] = fmaf(ov, w0.x, acc[0]); acc[1] = fmaf(ov, w0.y, acc[1]);
            acc[2] = fmaf(ov, w0.z, acc[2]); acc[3] = fmaf(ov, w0.w, acc[3]);
            acc[4] = fmaf(ov, w1.x, acc[4]); acc[5] = fmaf(ov, w1.y, acc[5]);
            acc[6] = fmaf(ov, w1.z, acc[6]); acc[7] = fmaf(ov, w1.w, acc[7]);
        }
        size_t base = (size_t)r * DD + j * 16 + s0;
        #pragma unroll
        for (int u = 0; u < 8; u++) H[base + u] = acc[u];
        #pragma unroll
        for (int u = 0; u < 8; u++) Hf[base + u] = __float2half(acc[u]);
    }
}

// ---------------------------------------------------------------------------
// Weight transpose to fp16 — all 12 matrices, one launch; __half2 stores
// ---------------------------------------------------------------------------
struct TsplitArgs { const float* w[12]; };

__global__ __launch_bounds__(256) void tsplit_all_kernel(
    TsplitArgs args, __half* __restrict__ TBase)
{
    __shared__ float t[32][33];
    const int slot = blockIdx.z;
    const float* W = args.w[slot];
    __half* T = TBase + (size_t)slot * DSZ;

    const int bx = blockIdx.x, by = blockIdx.y;
    const int tx = threadIdx.x & 31, ty = threadIdx.x >> 5;
    #pragma unroll
    for (int i = 0; i < 4; i++) {
        int k = by * 32 + ty + i * 8;
        t[ty + i * 8][tx] = W[(size_t)k * 2048 + bx * 32 + tx];
    }
    __syncthreads();
    // store side: 16 k-pairs x 16 n per pass, __half2 writes
    const int sx = threadIdx.x & 15;   // k-pair index
    const int sy = threadIdx.x >> 4;   // 0..15
    #pragma unroll
    for (int i = 0; i < 2; i++) {
        int n  = bx * 32 + sy + i * 16;
        int k0 = by * 32 + sx * 2;
        __half2 hv;
        hv.x = __float2half(t[sx * 2][sy + i * 16]);
        hv.y = __float2half(t[sx * 2 + 1][sy + i * 16]);
        *(__half2*)(T + (size_t)n * 2048 + k0) = hv;
    }
}

// ---------------------------------------------------------------------------
// fp16 GEMM via mma.sync — 512 threads, 16 warps, warp tile 32x32,
// BK=64, 2-stage cp.async pipeline.
//   mode 0: C=acc+bias fp32 | 2: +resid fp32 | 3: relu->fp16 | 4: fp16 (no relu)
// ---------------------------------------------------------------------------
#define GEMM_THREADS   512
#define GEMM_BK        64
#define GEMM_LDS       72                       // padded row (elements)
#define GEMM_ARR_BYTES (128*GEMM_LDS*2)         // 18432
#define GEMM_STAGE     (2*GEMM_ARR_BYTES)       // 36864
#define GEMM_SMEM      (2*GEMM_STAGE)           // 73728

__device__ __forceinline__ void gemm_load_stage(
    const __half* A, const __half* B,
    uint32_t sbase, int buf, int m0, int n0, int kc, int tid)
{
    uint32_t sb = sbase + buf * GEMM_STAGE;
    const char* ga = (const char*)(A + (size_t)m0 * 2048 + kc);
    const char* gb = (const char*)(B + (size_t)n0 * 2048 + kc);
    #pragma unroll
    for (int j = 0; j < 2; j++) {
        int idx = tid + j * 512;           // 0..1023
        int row = idx >> 3;                // 0..127
        int cu  = idx & 7;                 // 8 x 16B = 128B per row
        uint32_t soff = row * (GEMM_LDS * 2) + cu * 16;
        size_t  goff = (size_t)row * 4096 + cu * 16;
        CP_ASYNC16(sb + soff, ga + goff);
        CP_ASYNC16(sb + GEMM_ARR_BYTES + soff, gb + goff);
    }
}

__global__ __launch_bounds__(GEMM_THREADS, 1)
void gemm_mma_kernel(
    const __half* __restrict__ A, const __half* __restrict__ B,
    const float* __restrict__ bias, const float* __restrict__ resid,
    float* __restrict__ C, __half* __restrict__ Of,
    int mode)
{
    extern __shared__ char dsm[];
    const uint32_t sbase = smem_u32(dsm);

    const int tid  = threadIdx.x;
    const int wid  = tid >> 5;
    const int lane = tid & 31;
    const int wm   = wid & 3;
    const int wn   = wid >> 2;
    const int m0   = blockIdx.y * 128;
    const int n0   = blockIdx.x * 128;

    const int aoff = (wm * 32 + (lane & 15)) * GEMM_LDS + (lane >> 4) * 8;
    const int boff = (wn * 32 + (lane >> 4) * 8 + (lane & 7)) * GEMM_LDS + ((lane >> 3) & 1) * 8;

    float acc[2][4][4];
    #pragma unroll
    for (int mt = 0; mt < 2; mt++)
        #pragma unroll
        for (int nt = 0; nt < 4; nt++)
            #pragma unroll
            for (int c = 0; c < 4; c++) acc[mt][nt][c] = 0.f;

    gemm_load_stage(A, B, sbase, 0, m0, n0, 0, tid);
    CP_COMMIT();
    CP_WAIT0();
    __syncthreads();

    const int NCHUNK = 2048 / GEMM_BK;   // 32
    for (int i = 0; i < NCHUNK; i++) {
        const int buf = i & 1;
        if (i + 1 < NCHUNK) {
            gemm_load_stage(A, B, sbase, buf ^ 1, m0, n0, (i + 1) * GEMM_BK, tid);
            CP_COMMIT();
        }

        const uint32_t aB = sbase + buf * GEMM_STAGE;
        const uint32_t bB = aB + GEMM_ARR_BYTES;

        #pragma unroll
        for (int kt = 0; kt < 4; kt++) {
            uint32_t af[2][4];
            #pragma unroll
            for (int mt = 0; mt < 2; mt++) {
                uint32_t ao = (aoff + mt * 16 * GEMM_LDS + kt * 16) * 2;
                ldsm_x4(af[mt], aB + ao);
            }
            #pragma unroll
            for (int np = 0; np < 2; np++) {
                uint32_t bo = (boff + np * 16 * GEMM_LDS + kt * 16) * 2;
                uint32_t bf[4];
                ldsm_x4(bf, bB + bo);
                #pragma unroll
                for (int half = 0; half < 2; half++) {
                    int nt = np * 2 + half;
                    #pragma unroll
                    for (int mt = 0; mt < 2; mt++)
                        mma_fp16(acc[mt][nt], af[mt], bf + half * 2);
                }
            }
        }

        CP_WAIT0();
        __syncthreads();
    }

    // epilogue
    const int g  = lane >> 2;
    const int t2 = lane & 3;
    #pragma unroll
    for (int mt = 0; mt < 2; mt++) {
        #pragma unroll
        for (int nt = 0; nt < 4; nt++) {
            int row = m0 + wm * 32 + mt * 16 + g;
            int col = n0 + wn * 32 + nt * 8 + t2 * 2;
            float b0 = __ldg(bias + col), b1 = __ldg(bias + col + 1);
            #pragma unroll
            for (int half = 0; half < 2; half++) {
                int rr = row + half * 8;
                float v0 = acc[mt][nt][half * 2 + 0] + b0;
                float v1 = acc[mt][nt][half * 2 + 1] + b1;
                size_t off = (size_t)rr * 2048 + col;
                if (mode >= 3) {
                    if (mode == 3) { v0 = fmaxf(v0, 0.f); v1 = fmaxf(v1, 0.f); }
                    __half2 hp; hp.x = __float2half(v0); hp.y = __float2half(v1);
                    *(uint32_t*)(Of + off) = *(uint32_t*)&hp;
                } else {
                    if (mode == 2) {
                        const float2 rp = *(const float2*)(resid + off);
                        v0 += rp.x; v1 += rp.y;
                    }
                    float2 o; o.x = v0; o.y = v1;
                    *(float2*)(C + off) = o;
                }
            }
        }
    }
}

// ---------------------------------------------------------------------------
// Attention — fp16 in, register-tiled, parallel softmax, fp16 out
// ---------------------------------------------------------------------------
#define ATTN_SMEM_BYTES ((8256 + 8256 + 8192 + 4160) * 4)

__global__ __launch_bounds__(256) void attn_kernel(
    const __half* __restrict__ Qf, const __half* __restrict__ Kf,
    const __half* __restrict__ Vf, __half* __restrict__ AOf)
{
    extern __shared__ float sm[];
    float* sq = sm;            // 64*129
    float* sk = sq + 8256;     // 64*129
    float* sv = sk + 8256;     // 64*128
    float* sc = sv + 8192;     // 64*65

    const int tid = threadIdx.x;
    const int b   = blockIdx.x >> 4;
    const int hd  = blockIdx.x & 15;
    const size_t base = (size_t)(b * TT) * DD + hd * DH;
    const float SCALE = 0.08838834764831845f;   // 1/sqrt(128)

    for (int idx = tid; idx < 8192; idx += 256) {
        int t = idx >> 7, d = idx & 127;
        size_t g = base + (size_t)t * DD + d;
        sq[t * 129 + d] = __half2float(Qf[g]) * SCALE;
        sk[t * 129 + d] = __half2float(Kf[g]);
        sv[idx]         = __half2float(Vf[g]);
    }
    __syncthreads();

    // scores: 4x4 per thread
    {
        const int a    = tid >> 4;   // 0..15
        const int bcol = tid & 15;   // 0..15
        float acc[4][4];
        #pragma unroll
        for (int u = 0; u < 4; u++)
            #pragma unroll
            for (int w = 0; w < 4; w++) acc[u][w] = 0.f;

        for (int d = 0; d < 128; d++) {
            float qv[4], kv[4];
            #pragma unroll
            for (int u = 0; u < 4; u++) qv[u] = sq[(a + u * 16) * 129 + d];
            #pragma unroll
            for (int w = 0; w < 4; w++) kv[w] = sk[(bcol + w * 16) * 129 + d];
            #pragma unroll
            for (int u = 0; u < 4; u++)
                #pragma unroll
                for (int w = 0; w < 4; w++)
                    acc[u][w] = fmaf(qv[u], kv[w], acc[u][w]);
        }
        #pragma unroll
        for (int u = 0; u < 4; u++)
            #pragma unroll
            for (int w = 0; w < 4; w++)
                sc[(a + u * 16) * 65 + bcol + w * 16] = acc[u][w];
    }
    __syncthreads();

    // row softmax: 4 threads per row (quad shuffles)
    {
        const int row  = tid >> 2;
        const int part = tid & 3;
        float* rp = sc + row * 65 + part * 16;
        float m = -1e30f;
        #pragma unroll
        for (int i = 0; i < 16; i++) m = fmaxf(m, rp[i]);
        m = fmaxf(m, __shfl_xor_sync(0xffffffffu, m, 1));
        m = fmaxf(m, __shfl_xor_sync(0xffffffffu, m, 2));
        float s = 0.f;
        #pragma unroll
        for (int i = 0; i < 16; i++) { float e = __expf(rp[i] - m); rp[i] = e; s += e; }
        s += __shfl_xor_sync(0xffffffffu, s, 1);
        s += __shfl_xor_sync(0xffffffffu, s, 2);
        float inv = 1.0f / s;
        #pragma unroll
        for (int i = 0; i < 16; i++) rp[i] *= inv;
    }
    __syncthreads();

    // ao: 8 t x 4 d per thread (alpha loads are warp-uniform broadcasts)
    {
        const int tg = tid >> 5;    // 0..7 (fixed per warp)
        const int dg = tid & 31;    // d = dg + 32*dd
        float acc[8][4];
        #pragma unroll
        for (int u = 0; u < 8; u++)
            #pragma unroll
            for (int dd = 0; dd < 4; dd++) acc[u][dd] = 0.f;

        for (int t2 = 0; t2 < 64; t2++) {
            float av[8], vv[4];
            #pragma unroll
            for (int u = 0; u < 8; u++) av[u] = sc[(tg * 8 + u) * 65 + t2];
            #pragma unroll
            for (int dd = 0; dd < 4; dd++) vv[dd] = sv[t2 * 128 + dg + dd * 32];
            #pragma unroll
            for (int u = 0; u < 8; u++)
                #pragma unroll
                for (int dd = 0; dd < 4; dd++)
                    acc[u][dd] = fmaf(av[u], vv[dd], acc[u][dd]);
        }
        #pragma unroll
        for (int u = 0; u < 8; u++) {
            int t = tg * 8 + u;
            #pragma unroll
            for (int dd = 0; dd < 4; dd++)
                AOf[base + (size_t)t * DD + dg + dd * 32] = __float2half(acc[u][dd]);
        }
    }
}

// ---------------------------------------------------------------------------
// LayerNorm: fp32 out + fp16 out
// ---------------------------------------------------------------------------
__global__ __launch_bounds__(256) void ln_kernel(
    const float* __restrict__ x, float* __restrict__ y,
    const float* __restrict__ g, const float* __restrict__ b,
    __half* __restrict__ Yf)
{
    __shared__ float red[256];
    const int row = blockIdx.x, tid = threadIdx.x;
    const float* xr = x + (size_t)row * DD;

    float s = 0.f;
    for (int i = tid; i < DD; i += 256) s += xr[i];
    red[tid] = s; __syncthreads();
    for (int st = 128; st > 0; st >>= 1) { if (tid < st) red[tid] += red[tid + st]; __syncthreads(); }
    float mu = red[0] * (1.0f / DD);
    __syncthreads();

    float v = 0.f;
    for (int i = tid; i < DD; i += 256) { float d = xr[i] - mu; v += d * d; }
    red[tid] = v; __syncthreads();
    for (int st = 128; st > 0; st >>= 1) { if (tid < st) red[tid] += red[tid + st]; __syncthreads(); }
    float var = red[0] * (1.0f / DD);
    float inv = 1.0f / sqrtf(var + 1e-5f);

    float* yr = y + (size_t)row * DD;
    __half* fr = Yf + (size_t)row * DD;
    for (int i = tid; i < DD; i += 256) {
        float val = (xr[i] - mu) * inv * g[i] + b[i];
        yr[i] = val;
        fr[i] = __float2half(val);
    }
}

// ---------------------------------------------------------------------------
// Final projection
// ---------------------------------------------------------------------------
__global__ void out_kernel(const float* __restrict__ H, const float* __restrict__ Wout,
                           const float* __restrict__ bout, float* __restrict__ out)
{
    int b = blockIdx.x;
    int o = threadIdx.x >> 5;
    int lane = threadIdx.x & 31;
    if (o >= NOUT) return;
    const float* h = H + (size_t)(b * TT + TT - 1) * DD;
    float acc = 0.f;
    for (int i = lane; i < DD; i += 32)
        acc += h[i] * Wout[i * NOUT + o];
    #pragma unroll
    for (int s = 16; s > 0; s >>= 1)
        acc += __shfl_down_sync(0xffffffffu, acc, s);
    if (lane == 0) out[b * NOUT + o] = acc + bout[o];
}

// ---------------------------------------------------------------------------
// Launch
// ---------------------------------------------------------------------------
extern "C" void kernel_launch(void* const* d_in, const int* in_sizes, int n_in,
                              void* d_out, int out_size)
{
    (void)in_sizes; (void)n_in; (void)out_size;

    const float* X      = (const float*)d_in[0];
    const float* V_Adap = (const float*)d_in[1];
    const float* Wl     = (const float*)d_in[2];
    const float* bl     = (const float*)d_in[3];
    const float* Wr     = (const float*)d_in[4];
    const float* br     = (const float*)d_in[5];
    const float* att    = (const float*)d_in[6];
    const float* gbias  = (const float*)d_in[7];
    const float* Wfc    = (const float*)d_in[8];
    const float* bfc    = (const float*)d_in[9];
    const float* Wq     = (const float*)d_in[10];
    const float* bq     = (const float*)d_in[11];
    const float* Wk     = (const float*)d_in[12];
    const float* bk     = (const float*)d_in[13];
    const float* Wv     = (const float*)d_in[14];
    const float* bv     = (const float*)d_in[15];
    const float* Wo     = (const float*)d_in[16];
    const float* bo     = (const float*)d_in[17];
    const float* ln1g   = (const float*)d_in[18];
    const float* ln1b   = (const float*)d_in[19];
    const float* W1     = (const float*)d_in[20];
    const float* b1     = (const float*)d_in[21];
    const float* W2     = (const float*)d_in[22];
    const float* b2     = (const float*)d_in[23];
    const float* ln2g   = (const float*)d_in[24];
    const float* ln2b   = (const float*)d_in[25];
    const float* Wout   = (const float*)d_in[26];
    const float* bout   = (const float*)d_in[27];
    const int*   cls    = (const int*)d_in[28];

    float* base = nullptr;
    unsigned char* maskp = nullptr;
    __half *wt = nullptr, *af = nullptr, *bf = nullptr;
    cudaGetSymbolAddress((void**)&base,  g_scratch);
    cudaGetSymbolAddress((void**)&maskp, g_mask);
    cudaGetSymbolAddress((void**)&wt,    g_wt);
    cudaGetSymbolAddress((void**)&af,    g_a);
    cudaGetSymbolAddress((void**)&bf,    g_b);

    float* h  = base + 0ull * DSZ;
    float* t  = base + 6ull * DSZ;
    // fp16 q/k/v live in scratch slots 1-2 (3*DSZ halfs = 1.5 fp32 slots)
    __half* qh = (__half*)(base + 1ull * DSZ);
    __half* kh = qh + DSZ;
    __half* vh = kh + DSZ;

    cudaFuncSetAttribute(gat_kernel,      cudaFuncAttributeMaxDynamicSharedMemorySize, GAT_SMEM_BYTES);
    cudaFuncSetAttribute(attn_kernel,     cudaFuncAttributeMaxDynamicSharedMemorySize, ATTN_SMEM_BYTES);
    cudaFuncSetAttribute(gemm_mma_kernel, cudaFuncAttributeMaxDynamicSharedMemorySize, GEMM_SMEM);

    mask_kernel<<<NN, NN>>>(V_Adap, cls, maskp);
    gat_kernel<<<ROWS, 256, GAT_SMEM_BYTES>>>(X, Wl, bl, Wr, br, att, gbias, Wfc, bfc, maskp,
                                              h, af);

    // transpose all 12 weight matrices to fp16 in ONE launch
    {
        TsplitArgs ta;
        for (int l = 0; l < LAYERS; l++) {
            ta.w[l * 6 + 0] = Wq + (size_t)l * DSZ;
            ta.w[l * 6 + 1] = Wk + (size_t)l * DSZ;
            ta.w[l * 6 + 2] = Wv + (size_t)l * DSZ;
            ta.w[l * 6 + 3] = Wo + (size_t)l * DSZ;
            ta.w[l * 6 + 4] = W1 + (size_t)l * DSZ;
            ta.w[l * 6 + 5] = W2 + (size_t)l * DSZ;
        }
        dim3 tg(64, 64, 12);
        tsplit_all_kernel<<<tg, 256>>>(ta, wt);
    }

    dim3 gg(16, 16);
    for (int l = 0; l < LAYERS; l++) {
        __half* w0  = wt + (size_t)(l * 6 + 0) * DSZ;
        __half* w1p = wt + (size_t)(l * 6 + 1) * DSZ;
        __half* w2p = wt + (size_t)(l * 6 + 2) * DSZ;
        __half* w3  = wt + (size_t)(l * 6 + 3) * DSZ;
        __half* w4  = wt + (size_t)(l * 6 + 4) * DSZ;
        __half* w5  = wt + (size_t)(l * 6 + 5) * DSZ;

        // QKV -> fp16 directly (mode 4)
        gemm_mma_kernel<<<gg, GEMM_THREADS, GEMM_SMEM>>>(af, w0, bq + l * DD,
                                                nullptr, nullptr, qh, 4);
        gemm_mma_kernel<<<gg, GEMM_THREADS, GEMM_SMEM>>>(af, w1p, bk + l * DD,
                                                nullptr, nullptr, kh, 4);
        gemm_mma_kernel<<<gg, GEMM_THREADS, GEMM_SMEM>>>(af, w2p, bv + l * DD,
                                                nullptr, nullptr, vh, 4);
        attn_kernel<<<BB * NHEADS, 256, ATTN_SMEM_BYTES>>>(qh, kh, vh, af);
        gemm_mma_kernel<<<gg, GEMM_THREADS, GEMM_SMEM>>>(af, w3, bo + l * DD,
                                                h, t, nullptr, 2);
        ln_kernel<<<ROWS, 256>>>(t, h, ln1g + l * DD, ln1b + l * DD, af);
        gemm_mma_kernel<<<gg, GEMM_THREADS, GEMM_SMEM>>>(af, w4, b1 + l * DFF,
                                                nullptr, nullptr, bf, 3);
        gemm_mma_kernel<<<gg, GEMM_THREADS, GEMM_SMEM>>>(bf, w5, b2 + l * DD,
                                                h, t, nullptr, 2);
        ln_kernel<<<ROWS, 256>>>(t, h, ln2g + l * DD, ln2b + l * DD, af);
    }

    out_kernel<<<BB, 320>>>(h, Wout, bout, (float*)d_out);
}